// round 15
// baseline (speedup 1.0000x reference)
#include <cuda_runtime.h>
#include <cuda_bf16.h>
#include <cstdint>
#include <math.h>

// ---------------------------------------------------------------------------
// Problem constants
// ---------------------------------------------------------------------------
#define QLEN     1024
#define HID      3584
#define NHEADS   28
#define NKV      4
#define HDIM     128
#define PASTLEN  3072
#define KVTOT    4096
#define NREP     7

// ---------------------------------------------------------------------------
// Scratch (device globals)
// ---------------------------------------------------------------------------
__device__ float g_Q[QLEN * HID];
__device__ float g_K[QLEN * (NKV*HDIM)];
__device__ float g_V[QLEN * (NKV*HDIM)];

__device__ __nv_bfloat16 g_hid_hi[QLEN * HID];
__device__ __nv_bfloat16 g_hid_lo[QLEN * HID];
__device__ __nv_bfloat16 g_att_hi[QLEN * HID];
__device__ __nv_bfloat16 g_att_lo[QLEN * HID];
__device__ __nv_bfloat16 g_WqT_hi[HID * HID];
__device__ __nv_bfloat16 g_WqT_lo[HID * HID];
__device__ __nv_bfloat16 g_WkT_hi[(NKV*HDIM) * HID];
__device__ __nv_bfloat16 g_WkT_lo[(NKV*HDIM) * HID];
__device__ __nv_bfloat16 g_WvT_hi[(NKV*HDIM) * HID];
__device__ __nv_bfloat16 g_WvT_lo[(NKV*HDIM) * HID];
__device__ __nv_bfloat16 g_WoT_hi[HID * HID];
__device__ __nv_bfloat16 g_WoT_lo[HID * HID];

__device__ __nv_bfloat16 g_Qb_hi[QLEN * HID];
__device__ __nv_bfloat16 g_Qb_lo[QLEN * HID];
__device__ __nv_bfloat16 g_Kb_hi[NKV * KVTOT * HDIM];
__device__ __nv_bfloat16 g_Kb_lo[NKV * KVTOT * HDIM];
__device__ __nv_bfloat16 g_Vb_hi[NKV * KVTOT * HDIM];
__device__ __nv_bfloat16 g_Vb_lo[NKV * KVTOT * HDIM];

__device__ float g_Op[2 * NHEADS * QLEN * HDIM];
__device__ float g_Ml[2 * NHEADS * QLEN * 2];

// ---------------------------------------------------------------------------
// Helpers (plain-sm_103-legal: cp.async + ldmatrix + mma.sync only)
// ---------------------------------------------------------------------------
__device__ __forceinline__ uint32_t smem_to_u32(const void* p) {
    uint32_t a;
    asm("{ .reg .u64 t; cvta.to.shared.u64 t, %1; cvt.u32.u64 %0, t; }" : "=r"(a) : "l"(p));
    return a;
}
#define SMEM_SWIZZLE_128B(b) ((b) ^ (((b) >> 3) & 0x70))

__device__ __forceinline__ void cp_async16(uint32_t dst, const void* src) {
    asm volatile("cp.async.cg.shared.global [%0], [%1], 16;" :: "r"(dst), "l"(src) : "memory");
}
__device__ __forceinline__ void cp_commit() {
    asm volatile("cp.async.commit_group;" ::: "memory");
}
template <int N> __device__ __forceinline__ void cp_wait() {
    asm volatile("cp.async.wait_group %0;" :: "n"(N) : "memory");
}

__device__ __forceinline__ void ldm_x4(uint32_t* r, uint32_t addr) {
    asm volatile("ldmatrix.sync.aligned.m8n8.x4.shared.b16 {%0,%1,%2,%3}, [%4];"
                 : "=r"(r[0]), "=r"(r[1]), "=r"(r[2]), "=r"(r[3]) : "r"(addr));
}
__device__ __forceinline__ void ldm_x4t(uint32_t* r, uint32_t addr) {
    asm volatile("ldmatrix.sync.aligned.m8n8.x4.trans.shared.b16 {%0,%1,%2,%3}, [%4];"
                 : "=r"(r[0]), "=r"(r[1]), "=r"(r[2]), "=r"(r[3]) : "r"(addr));
}
__device__ __forceinline__ void mma_bf16(float* c, const uint32_t* a, const uint32_t* b) {
    asm volatile("mma.sync.aligned.m16n8k16.row.col.f32.bf16.bf16.f32 "
                 "{%0,%1,%2,%3}, {%4,%5,%6,%7}, {%8,%9}, {%0,%1,%2,%3};"
                 : "+f"(c[0]), "+f"(c[1]), "+f"(c[2]), "+f"(c[3])
                 : "r"(a[0]), "r"(a[1]), "r"(a[2]), "r"(a[3]), "r"(b[0]), "r"(b[1]));
}
__device__ __forceinline__ float fexp2(float x) {
    float y; asm("ex2.approx.ftz.f32 %0, %1;" : "=f"(y) : "f"(x)); return y;
}
__device__ __forceinline__ uint32_t packbf(__nv_bfloat16 a, __nv_bfloat16 b) {
    __nv_bfloat162 t(a, b);
    return *(uint32_t*)&t;
}

// ---------------------------------------------------------------------------
// Weight transposes + hidden-state split in one launch.
// z 0..3: W [K=3584][N] f32 -> T [N][K] bf16 hi/lo.  z == 4: split(hid).
// ---------------------------------------------------------------------------
__global__ void prep_kernel(const float* __restrict__ Wq,
                            const float* __restrict__ Wk,
                            const float* __restrict__ Wv,
                            const float* __restrict__ Wo,
                            const float* __restrict__ hid,
                            __nv_bfloat16* __restrict__ qhi, __nv_bfloat16* __restrict__ qlo,
                            __nv_bfloat16* __restrict__ khi, __nv_bfloat16* __restrict__ klo,
                            __nv_bfloat16* __restrict__ vhi, __nv_bfloat16* __restrict__ vlo,
                            __nv_bfloat16* __restrict__ ohi, __nv_bfloat16* __restrict__ olo,
                            __nv_bfloat16* __restrict__ hhi, __nv_bfloat16* __restrict__ hlo)
{
    const int z = blockIdx.z;
    if (z == 4) {                         // split(hid): 3584 flat blocks x 256 f4
        int b = blockIdx.y * 112 + blockIdx.x;
        if (b >= 3584) return;
        int i = b * 256 + threadIdx.y * 32 + threadIdx.x;
        float4 x = ((const float4*)hid)[i];
        float v[4] = { x.x, x.y, x.z, x.w };
        __nv_bfloat16 h[4], l[4];
        #pragma unroll
        for (int j = 0; j < 4; j++) {
            h[j] = __float2bfloat16(v[j]);
            l[j] = __float2bfloat16(v[j] - __bfloat162float(h[j]));
        }
        __nv_bfloat162* H = (__nv_bfloat162*)hhi;
        __nv_bfloat162* L = (__nv_bfloat162*)hlo;
        H[2*i]   = __nv_bfloat162(h[0], h[1]);
        H[2*i+1] = __nv_bfloat162(h[2], h[3]);
        L[2*i]   = __nv_bfloat162(l[0], l[1]);
        L[2*i+1] = __nv_bfloat162(l[2], l[3]);
        return;
    }

    const float* W; __nv_bfloat16 *Thi, *Tlo; int N;
    if      (z == 0) { W = Wq; Thi = qhi; Tlo = qlo; N = HID; }
    else if (z == 1) { W = Wk; Thi = khi; Tlo = klo; N = NKV*HDIM; }
    else if (z == 2) { W = Wv; Thi = vhi; Tlo = vlo; N = NKV*HDIM; }
    else             { W = Wo; Thi = ohi; Tlo = olo; N = HID; }
    if (blockIdx.x * 32 >= N) return;

    __shared__ float t[32][33];
    int n0 = blockIdx.x * 32, k0 = blockIdx.y * 32;
    int tx = threadIdx.x, ty = threadIdx.y;
    #pragma unroll
    for (int r = 0; r < 4; r++)
        t[ty + r*8][tx] = W[(size_t)(k0 + ty + r*8) * N + n0 + tx];
    __syncthreads();
    #pragma unroll
    for (int r = 0; r < 4; r++) {
        int n = n0 + ty + r*8;
        float v = t[tx][ty + r*8];
        __nv_bfloat16 h = __float2bfloat16(v);
        __nv_bfloat16 l = __float2bfloat16(v - __bfloat162float(h));
        Thi[(size_t)n * HID + k0 + tx] = h;
        Tlo[(size_t)n * HID + k0 + tx] = l;
    }
}

// Pack KV cache rows only: y=0 K-cache, y=1 V-cache
__global__ void pack_kv_kernel(const float* __restrict__ kcache,
                               const float* __restrict__ vcache,
                               __nv_bfloat16* __restrict__ khi,
                               __nv_bfloat16* __restrict__ klo,
                               __nv_bfloat16* __restrict__ vhi,
                               __nv_bfloat16* __restrict__ vlo)
{
    int i = blockIdx.x * blockDim.x + threadIdx.x;
    if (i >= NKV * PASTLEN * 32) return;
    const float* cache = blockIdx.y ? vcache : kcache;
    __nv_bfloat16* hi = blockIdx.y ? vhi : khi;
    __nv_bfloat16* lo = blockIdx.y ? vlo : klo;
    int kvh = i / (PASTLEN * 32);
    int rem = i % (PASTLEN * 32);
    int pos = rem >> 5;
    int d4  = (rem & 31) * 4;
    float4 v = *(const float4*)(cache + ((size_t)(kvh * PASTLEN + pos) * HDIM + d4));
    float a[4] = { v.x, v.y, v.z, v.w };
    __nv_bfloat16 h[4], l[4];
    #pragma unroll
    for (int j = 0; j < 4; j++) {
        h[j] = __float2bfloat16(a[j]);
        l[j] = __float2bfloat16(a[j] - __bfloat162float(h[j]));
    }
    size_t o = ((size_t)(kvh * KVTOT + pos) * HDIM + d4) >> 1;
    ((__nv_bfloat162*)hi)[o]     = __nv_bfloat162(h[0], h[1]);
    ((__nv_bfloat162*)hi)[o + 1] = __nv_bfloat162(h[2], h[3]);
    ((__nv_bfloat162*)lo)[o]     = __nv_bfloat162(l[0], l[1]);
    ((__nv_bfloat162*)lo)[o + 1] = __nv_bfloat162(l[2], l[3]);
}

// ---------------------------------------------------------------------------
// mma.sync split-precision GEMM core v5 (R12 WIN, unchanged).
// CTA tile 128x128, 4 warps of 64x64, 2 CTAs/SM (97KB smem).
// Phase 1: stage {Ahi|Bhi|Blo} 48KB, 2-ring, 2 passes/stage.
// Phase 2: stage {Alo|Bhi} 32KB, 3-ring.
// ---------------------------------------------------------------------------
#define MM_SMEM  99328

__device__ __forceinline__ void mm_tile(
    const __nv_bfloat16* __restrict__ Ahi, const __nv_bfloat16* __restrict__ Alo,
    const __nv_bfloat16* __restrict__ Bhi, const __nv_bfloat16* __restrict__ Blo,
    const float* __restrict__ bias, float* __restrict__ C, int ldc,
    int m0, int n0, int kbase, int segst, char* smem)
{
    const uint32_t sb   = smem_to_u32(smem);
    const uint32_t DATA = (sb + 1023u) & ~1023u;
    const int tid = threadIdx.x, wid = tid >> 5, lane = tid & 31;
    const int wm = (wid & 1) * 64;
    const int wn = (wid >> 1) * 64;

    uint32_t sw8[8]; int gr8[8], gc8[8];
    #pragma unroll
    for (int i = 0; i < 8; i++) {
        int c = tid + i * 128;
        gr8[i] = c >> 3;
        gc8[i] = (c & 7) * 8;
        sw8[i] = SMEM_SWIZZLE_128B((uint32_t)((c >> 3) * 128 + (c & 7) * 16));
    }

    auto load1 = [&](int g) {
        int kk = kbase + g * 64;
        uint32_t ab = DATA + (uint32_t)(g & 1) * 49152u;
        #pragma unroll
        for (int i = 0; i < 8; i++)
            cp_async16(ab + sw8[i], Ahi + (size_t)(m0 + gr8[i]) * HID + kk + gc8[i]);
        #pragma unroll
        for (int i = 0; i < 8; i++)
            cp_async16(ab + 16384u + sw8[i], Bhi + (size_t)(n0 + gr8[i]) * HID + kk + gc8[i]);
        #pragma unroll
        for (int i = 0; i < 8; i++)
            cp_async16(ab + 32768u + sw8[i], Blo + (size_t)(n0 + gr8[i]) * HID + kk + gc8[i]);
        cp_commit();
    };
    auto load2 = [&](int g) {
        int kk = kbase + g * 64;
        uint32_t ab = DATA + (uint32_t)(g % 3) * 32768u;
        #pragma unroll
        for (int i = 0; i < 8; i++)
            cp_async16(ab + sw8[i], Alo + (size_t)(m0 + gr8[i]) * HID + kk + gc8[i]);
        #pragma unroll
        for (int i = 0; i < 8; i++)
            cp_async16(ab + 16384u + sw8[i], Bhi + (size_t)(n0 + gr8[i]) * HID + kk + gc8[i]);
        cp_commit();
    };

    float acc[4][8][4];
    #pragma unroll
    for (int a = 0; a < 4; a++)
        #pragma unroll
        for (int b = 0; b < 8; b++)
            #pragma unroll
            for (int c = 0; c < 4; c++) acc[a][b][c] = 0.0f;

    const int a_row = wm + (lane & 15);
    const int a_kb  = (lane >> 4) * 16;
    const int b_row = wn + ((lane >> 4) & 1) * 8 + (lane & 7);
    const int b_kb  = ((lane >> 3) & 1) * 16;

    // ---------------- phase 1: AhiBhi + AhiBlo ----------------
    load1(0);
    for (int g = 0; g < segst; g++) {
        cp_wait<0>();
        __syncthreads();
        if (g + 1 < segst) load1(g + 1);

        uint32_t ab = DATA + (uint32_t)(g & 1) * 49152u;

        #pragma unroll
        for (int ks = 0; ks < 4; ks++) {
            int kin = ks * 32;
            uint32_t aF[4][4];
            #pragma unroll
            for (int mi = 0; mi < 4; mi++) {
                uint32_t byte = (uint32_t)((a_row + mi * 16) * 128 + kin + a_kb);
                ldm_x4(aF[mi], ab + SMEM_SWIZZLE_128B(byte));
            }
            #pragma unroll
            for (int comp = 0; comp < 2; comp++) {
                uint32_t bb = ab + 16384u + (uint32_t)comp * 16384u;
                uint32_t bF[8][2];
                #pragma unroll
                for (int nb = 0; nb < 4; nb++) {
                    uint32_t byte = (uint32_t)((b_row + nb * 16) * 128 + kin + b_kb);
                    uint32_t r[4];
                    ldm_x4(r, bb + SMEM_SWIZZLE_128B(byte));
                    bF[nb*2+0][0] = r[0]; bF[nb*2+0][1] = r[1];
                    bF[nb*2+1][0] = r[2]; bF[nb*2+1][1] = r[3];
                }
                #pragma unroll
                for (int mi = 0; mi < 4; mi++)
                    #pragma unroll
                    for (int ni = 0; ni < 8; ni++)
                        mma_bf16(acc[mi][ni], aF[mi], bF[ni]);
            }
        }
    }
    __syncthreads();

    // ---------------- phase 2: AloBhi ----------------
    load2(0); load2(1);
    for (int g = 0; g < segst; g++) {
        if (g < segst - 1) cp_wait<1>();
        else               cp_wait<0>();
        __syncthreads();
        if (g + 2 < segst) load2(g + 2);

        uint32_t ab = DATA + (uint32_t)(g % 3) * 32768u;
        uint32_t bb = ab + 16384u;

        #pragma unroll
        for (int ks = 0; ks < 4; ks++) {
            int kin = ks * 32;
            uint32_t aF[4][4];
            #pragma unroll
            for (int mi = 0; mi < 4; mi++) {
                uint32_t byte = (uint32_t)((a_row + mi * 16) * 128 + kin + a_kb);
                ldm_x4(aF[mi], ab + SMEM_SWIZZLE_128B(byte));
            }
            uint32_t bF[8][2];
            #pragma unroll
            for (int nb = 0; nb < 4; nb++) {
                uint32_t byte = (uint32_t)((b_row + nb * 16) * 128 + kin + b_kb);
                uint32_t r[4];
                ldm_x4(r, bb + SMEM_SWIZZLE_128B(byte));
                bF[nb*2+0][0] = r[0]; bF[nb*2+0][1] = r[1];
                bF[nb*2+1][0] = r[2]; bF[nb*2+1][1] = r[3];
            }
            #pragma unroll
            for (int mi = 0; mi < 4; mi++)
                #pragma unroll
                for (int ni = 0; ni < 8; ni++)
                    mma_bf16(acc[mi][ni], aF[mi], bF[ni]);
        }
    }

    const int group = lane >> 2, tig = lane & 3;
    #pragma unroll
    for (int mi = 0; mi < 4; mi++) {
        #pragma unroll
        for (int ni = 0; ni < 8; ni++) {
            int r0 = m0 + wm + mi * 16 + group;
            int c0 = n0 + wn + ni * 8 + tig * 2;
            float b0 = 0.f, b1 = 0.f;
            if (bias) { b0 = bias[c0]; b1 = bias[c0 + 1]; }
            float2 v0 = make_float2(acc[mi][ni][0] + b0, acc[mi][ni][1] + b1);
            float2 v1 = make_float2(acc[mi][ni][2] + b0, acc[mi][ni][3] + b1);
            *(float2*)(C + (size_t)r0 * ldc + c0)       = v0;
            *(float2*)(C + (size_t)(r0 + 8) * ldc + c0) = v1;
        }
    }
}

// Fused QKV projection: grid (36, 8), 128 threads, 2 CTAs/SM
__global__ __launch_bounds__(128)
void qkv_mm_kernel(const __nv_bfloat16* __restrict__ Ahi, const __nv_bfloat16* __restrict__ Alo,
                   const __nv_bfloat16* __restrict__ qHi, const __nv_bfloat16* __restrict__ qLo,
                   const __nv_bfloat16* __restrict__ kHi, const __nv_bfloat16* __restrict__ kLo,
                   const __nv_bfloat16* __restrict__ vHi, const __nv_bfloat16* __restrict__ vLo,
                   const float* __restrict__ bq, const float* __restrict__ bk,
                   const float* __restrict__ bv,
                   float* __restrict__ gQ, float* __restrict__ gK, float* __restrict__ gV)
{
    extern __shared__ char smem[];
    const int bx = blockIdx.x, m0 = blockIdx.y * 128;
    if (bx < 28)
        mm_tile(Ahi, Alo, qHi, qLo, bq, gQ, HID, m0, bx * 128, 0, 56, smem);
    else if (bx < 32)
        mm_tile(Ahi, Alo, kHi, kLo, bk, gK, NKV*HDIM, m0, (bx - 28) * 128, 0, 56, smem);
    else
        mm_tile(Ahi, Alo, vHi, vLo, bv, gV, NKV*HDIM, m0, (bx - 32) * 128, 0, 56, smem);
}

// Output projection, split-K x2: grid (28, 8, 2) -> partial buffers
__global__ __launch_bounds__(128)
void oproj_kernel(const __nv_bfloat16* __restrict__ Ahi, const __nv_bfloat16* __restrict__ Alo,
                  const __nv_bfloat16* __restrict__ Bhi, const __nv_bfloat16* __restrict__ Blo,
                  float* __restrict__ P)
{
    extern __shared__ char smem[];
    const int z = blockIdx.z;
    mm_tile(Ahi, Alo, Bhi, Blo, nullptr, P + (size_t)z * QLEN * HID, HID,
            blockIdx.y * 128, blockIdx.x * 128, z * 1792, 28, smem);
}

// Sum the two split-K partials -> final output
__global__ void addout_kernel(const float* __restrict__ P, float* __restrict__ out)
{
    int i = blockIdx.x * blockDim.x + threadIdx.x;
    if (i >= QLEN * HID / 4) return;
    float4 a = ((const float4*)P)[i];
    float4 b = ((const float4*)(P + (size_t)QLEN * HID))[i];
    ((float4*)out)[i] = make_float4(a.x + b.x, a.y + b.y, a.z + b.z, a.w + b.w);
}

// ---------------------------------------------------------------------------
// RoPE + split-bf16 packing. y=0: Q rows; y=1: K rows; y=2: V new rows.
// ---------------------------------------------------------------------------
__global__ void rope_pack_kernel(const float* __restrict__ gQ, const float* __restrict__ gK,
                                 const float* __restrict__ gV, const int* __restrict__ pos,
                                 __nv_bfloat16* __restrict__ QbH, __nv_bfloat16* __restrict__ QbL,
                                 __nv_bfloat16* __restrict__ KbH, __nv_bfloat16* __restrict__ KbL,
                                 __nv_bfloat16* __restrict__ VbH, __nv_bfloat16* __restrict__ VbL)
{
    const int q = blockIdx.x;
    const int mode = blockIdx.y;

    if (mode == 2) {
        for (int t = threadIdx.x; t < NKV * HDIM; t += blockDim.x) {
            int kvh = t >> 7, d = t & 127;
            float v = gV[(size_t)q * (NKV*HDIM) + t];
            __nv_bfloat16 h = __float2bfloat16(v);
            __nv_bfloat16 l = __float2bfloat16(v - __bfloat162float(h));
            size_t dd = ((size_t)kvh * KVTOT + PASTLEN + q) * HDIM + d;
            VbH[dd] = h; VbL[dd] = l;
        }
        return;
    }

    __shared__ float cs[64], sn[64];
    const float p = (float)pos[q];
    if (threadIdx.x < 64) {
        float e = (float)threadIdx.x * (1.0f / 64.0f);
        float invf = 1.0f / powf(1000000.0f, e);
        sincosf(p * invf, &sn[threadIdx.x], &cs[threadIdx.x]);
    }
    __syncthreads();

    const int isK = mode;
    const int nh = isK ? NKV : NHEADS;
    const float* src = isK ? (gK + (size_t)q * (NKV*HDIM)) : (gQ + (size_t)q * HID);

    for (int t = threadIdx.x; t < nh * 64; t += blockDim.x) {
        int hh = t >> 6, i = t & 63;
        float s = sn[i], c = cs[i];
        const float* base = src + hh * HDIM;
        float x1 = base[i];
        float x2 = base[i + 64];
        float o1 = x1 * c - x2 * s;
        float o2 = x2 * c + x1 * s;
        __nv_bfloat16 h1 = __float2bfloat16(o1);
        __nv_bfloat16 l1 = __float2bfloat16(o1 - __bfloat162float(h1));
        __nv_bfloat16 h2 = __float2bfloat16(o2);
        __nv_bfloat16 l2 = __float2bfloat16(o2 - __bfloat162float(h2));
        size_t d1, d2;
        if (isK) {
            size_t row = (size_t)hh * KVTOT + PASTLEN + q;
            d1 = row * HDIM + i; d2 = d1 + 64;
            KbH[d1] = h1; KbL[d1] = l1;
            KbH[d2] = h2; KbL[d2] = l2;
        } else {
            d1 = (size_t)q * HID + hh * HDIM + i; d2 = d1 + 64;
            QbH[d1] = h1; QbL[d1] = l1;
            QbH[d2] = h2; QbL[d2] = l2;
        }
    }
}

// ---------------------------------------------------------------------------
// Tensorized flash attention (R12 WIN): 128 q x 64 kv, 256 threads, 1 CTA/SM,
// Q fragments register-cached; 2-way KV split; grid (8, 28, 2).
// ---------------------------------------------------------------------------
#define FL_SMEM (65536 * 3)

__global__ __launch_bounds__(256, 1)
void flash_mma_kernel(const __nv_bfloat16* __restrict__ Qhi,
                      const __nv_bfloat16* __restrict__ Qlo,
                      const __nv_bfloat16* __restrict__ Kbh,
                      const __nv_bfloat16* __restrict__ Kbl,
                      const __nv_bfloat16* __restrict__ Vbh,
                      const __nv_bfloat16* __restrict__ Vbl,
                      float* __restrict__ Op, float* __restrict__ Ml)
{
    extern __shared__ char smraw[];
    const uint32_t sb = smem_to_u32(smraw);
    const int tid = threadIdx.x, wid = tid >> 5, lane = tid & 31;
    const int qt = blockIdx.x, h = blockIdx.y, z = blockIdx.z;
    const int kvh = h / NREP;
    const int q0 = qt * 128;
    const int w16 = wid * 16;
    const int nt = 50 + 2 * qt;
    const int t0 = z ? (nt >> 1) : 0;
    const int t1 = z ? nt : (nt >> 1);

    #pragma unroll
    for (int i = 0; i < 16; i++) {
        int cg = tid + i * 256;
        int comp = i >> 3;
        int c = cg & 2047;
        int row = c >> 4, d8 = (c & 15) * 8;
        uint32_t dst = sb + (uint32_t)comp * 32768 + (uint32_t)((c >> 3) & 1) * 16384
                     + SMEM_SWIZZLE_128B((uint32_t)(row * 128 + (c & 7) * 16));
        const __nv_bfloat16* src = (comp ? Qlo : Qhi);
        cp_async16(dst, src + (size_t)(q0 + row) * HID + h * HDIM + d8);
    }
    cp_commit();

    auto load_stage = [&](int t) {
        uint32_t base = sb + 65536u + (uint32_t)(t & 1) * 65536u;
        int kvbase = t * 64;
        #pragma unroll
        for (int i = 0; i < 16; i++) {
            int comp = i >> 2;
            int c = (tid + i * 256) & 1023;
            int kv = c >> 4, d8 = (c & 15) * 8;
            uint32_t dst = base + (uint32_t)comp * 16384 + (uint32_t)((c >> 3) & 1) * 8192
                         + SMEM_SWIZZLE_128B((uint32_t)(kv * 128 + (c & 7) * 16));
            const __nv_bfloat16* src =
                (comp == 0) ? Kbh : (comp == 1) ? Kbl : (comp == 2) ? Vbh : Vbl;
            cp_async16(dst, src + ((size_t)(kvh * KVTOT + kvbase + kv) * HDIM + d8));
        }
        cp_commit();
    };

    load_stage(t0);

    cp_wait<1>();
    __syncthreads();
    uint32_t qFh[8][4], qFl[8][4];
    #pragma unroll
    for (int kc = 0; kc < 8; kc++) {
        uint32_t qoff = (uint32_t)((w16 + (lane & 15)) * 128 + (kc & 3) * 32 + (lane >> 4) * 16);
        uint32_t qa = sb + (uint32_t)(kc >> 2) * 16384 + SMEM_SWIZZLE_128B(qoff);
        ldm_x4(qFh[kc], qa);
        ldm_x4(qFl[kc], qa + 32768);
    }

    float Oacc[16][4];
    #pragma unroll
    for (int i = 0; i < 16; i++)
        #pragma unroll
        for (int j = 0; j < 4; j++) Oacc[i][j] = 0.0f;
    float m0 = -INFINITY, m1 = -INFINITY, l0 = 0.0f, l1 = 0.0f;

    const float SL = 0.08838834764831845f * 1.4426950408889634f;
    const int r0 = lane >> 2;

    for (int t = t0; t < t1; t++) {
        cp_wait<0>();
        __syncthreads();
        if (t + 1 < t1) load_stage(t + 1);

        const uint32_t stage = sb + 65536u + (uint32_t)(t & 1) * 65536u;
        const int kvbase = t * 64;

        float S[8][4];
        #pragma unroll
        for (int i = 0; i < 8; i++)
            #pragma unroll
            for (int j = 0; j < 4; j++) S[i][j] = 0.0f;

        #pragma unroll
        for (int kc = 0; kc < 8; kc++) {
            uint32_t kcol = (uint32_t)((kc & 3) * 32 + ((lane >> 3) & 1) * 16);
            #pragma unroll
            for (int np = 0; np < 4; np++) {
                uint32_t koff = (uint32_t)((np * 16 + ((lane >> 4) & 1) * 8 + (lane & 7)) * 128) + kcol;
                uint32_t ka = stage + (uint32_t)(kc >> 2) * 8192 + SMEM_SWIZZLE_128B(koff);
                uint32_t kh[4], kl[4];
                ldm_x4(kh, ka);
                ldm_x4(kl, ka + 16384);
                mma_bf16(S[2*np],   qFh[kc], kh);     mma_bf16(S[2*np],   qFl[kc], kh);
                mma_bf16(S[2*np],   qFh[kc], kl);
                mma_bf16(S[2*np+1], qFh[kc], kh + 2); mma_bf16(S[2*np+1], qFl[kc], kh + 2);
                mma_bf16(S[2*np+1], qFh[kc], kl + 2);
            }
        }

        if (t >= nt - 2) {
            const int lim0 = PASTLEN + q0 + w16 + r0;
            const int lim1 = lim0 + 8;
            #pragma unroll
            for (int nc = 0; nc < 8; nc++) {
                int col = kvbase + nc * 8 + (lane & 3) * 2;
                if (col     > lim0) S[nc][0] = -1e30f;
                if (col + 1 > lim0) S[nc][1] = -1e30f;
                if (col     > lim1) S[nc][2] = -1e30f;
                if (col + 1 > lim1) S[nc][3] = -1e30f;
            }
        }

        float mx0 = -INFINITY, mx1 = -INFINITY;
        #pragma unroll
        for (int nc = 0; nc < 8; nc++) {
            mx0 = fmaxf(mx0, fmaxf(S[nc][0], S[nc][1]));
            mx1 = fmaxf(mx1, fmaxf(S[nc][2], S[nc][3]));
        }
        mx0 = fmaxf(mx0, __shfl_xor_sync(0xffffffffu, mx0, 1));
        mx0 = fmaxf(mx0, __shfl_xor_sync(0xffffffffu, mx0, 2));
        mx1 = fmaxf(mx1, __shfl_xor_sync(0xffffffffu, mx1, 1));
        mx1 = fmaxf(mx1, __shfl_xor_sync(0xffffffffu, mx1, 2));
        float mn0 = fmaxf(m0, mx0 * SL);
        float mn1 = fmaxf(m1, mx1 * SL);
        float cor0 = fexp2(m0 - mn0);
        float cor1 = fexp2(m1 - mn1);
        m0 = mn0; m1 = mn1;

        uint32_t pH[8][2], pL[8][2];
        float rs0 = 0.0f, rs1 = 0.0f;
        #pragma unroll
        for (int nc = 0; nc < 8; nc++) {
            float p0 = fexp2(S[nc][0] * SL - mn0);
            float p1 = fexp2(S[nc][1] * SL - mn0);
            float p2 = fexp2(S[nc][2] * SL - mn1);
            float p3 = fexp2(S[nc][3] * SL - mn1);
            rs0 += p0 + p1;  rs1 += p2 + p3;
            __nv_bfloat16 h0 = __float2bfloat16(p0), h1 = __float2bfloat16(p1);
            __nv_bfloat16 h2 = __float2bfloat16(p2), h3 = __float2bfloat16(p3);
            pH[nc][0] = packbf(h0, h1);
            pH[nc][1] = packbf(h2, h3);
            pL[nc][0] = packbf(__float2bfloat16(p0 - __bfloat162float(h0)),
                               __float2bfloat16(p1 - __bfloat162float(h1)));
            pL[nc][1] = packbf(__float2bfloat16(p2 - __bfloat162float(h2)),
                               __float2bfloat16(p3 - __bfloat162float(h3)));
        }
        rs0 += __shfl_xor_sync(0xffffffffu, rs0, 1);
        rs0 += __shfl_xor_sync(0xffffffffu, rs0, 2);
        rs1 += __shfl_xor_sync(0xffffffffu, rs1, 1);
        rs1 += __shfl_xor_sync(0xffffffffu, rs1, 2);
        l0 = l0 * cor0 + rs0;
        l1 = l1 * cor1 + rs1;

        #pragma unroll
        for (int nc = 0; nc < 16; nc++) {
            Oacc[nc][0] *= cor0; Oacc[nc][1] *= cor0;
            Oacc[nc][2] *= cor1; Oacc[nc][3] *= cor1;
        }

        #pragma unroll
        for (int kc = 0; kc < 4; kc++) {
            uint32_t aH[4] = { pH[2*kc][0], pH[2*kc][1], pH[2*kc+1][0], pH[2*kc+1][1] };
            uint32_t aL[4] = { pL[2*kc][0], pL[2*kc][1], pL[2*kc+1][0], pL[2*kc+1][1] };
            uint32_t vrow = (uint32_t)(kc * 16 + ((lane >> 3) & 1) * 8 + (lane & 7));
            #pragma unroll
            for (int dp = 0; dp < 8; dp++) {
                uint32_t voff = vrow * 128 + (uint32_t)((dp & 3) * 32 + ((lane >> 4) & 1) * 16);
                uint32_t va = stage + 32768u + (uint32_t)(dp >> 2) * 8192 + SMEM_SWIZZLE_128B(voff);
                uint32_t vh[4], vl[4];
                ldm_x4t(vh, va);
                ldm_x4t(vl, va + 16384);
                mma_bf16(Oacc[2*dp],   aH, vh);     mma_bf16(Oacc[2*dp],   aL, vh);
                mma_bf16(Oacc[2*dp],   aH, vl);
                mma_bf16(Oacc[2*dp+1], aH, vh + 2); mma_bf16(Oacc[2*dp+1], aL, vh + 2);
                mma_bf16(Oacc[2*dp+1], aH, vl + 2);
            }
        }
    }

    const int rowa = q0 + w16 + r0;
    const size_t pb = ((size_t)(z * NHEADS + h) * QLEN);
    #pragma unroll
    for (int nc = 0; nc < 16; nc++) {
        int col = nc * 8 + (lane & 3) * 2;
        *(float2*)(Op + (pb + rowa) * HDIM + col) =
            make_float2(Oacc[nc][0], Oacc[nc][1]);
        *(float2*)(Op + (pb + rowa + 8) * HDIM + col) =
            make_float2(Oacc[nc][2], Oacc[nc][3]);
    }
    if ((lane & 3) == 0) {
        Ml[(pb + rowa) * 2]     = m0;
        Ml[(pb + rowa) * 2 + 1] = l0;
        Ml[(pb + rowa + 8) * 2]     = m1;
        Ml[(pb + rowa + 8) * 2 + 1] = l1;
    }
}

// Merge the two KV-split partials -> split-bf16 attention output
__global__ void combine_split_kernel(const float* __restrict__ Op,
                                     const float* __restrict__ Ml,
                                     __nv_bfloat16* __restrict__ aHi,
                                     __nv_bfloat16* __restrict__ aLo)
{
    int i = blockIdx.x * blockDim.x + threadIdx.x;
    if (i >= NHEADS * QLEN * (HDIM / 4)) return;
    int hq = i >> 5;
    int d4 = (i & 31) * 4;
    int h = hq >> 10, q = hq & 1023;
    size_t p0 = (size_t)h * QLEN + q;
    size_t p1 = (size_t)(NHEADS + h) * QLEN + q;
    float m0 = Ml[p0 * 2], l0 = Ml[p0 * 2 + 1];
    float m1 = Ml[p1 * 2], l1 = Ml[p1 * 2 + 1];
    float m = fmaxf(m0, m1);
    float s0 = fexp2(m0 - m), s1 = fexp2(m1 - m);
    float inv = 1.0f / (l0 * s0 + l1 * s1);
    s0 *= inv; s1 *= inv;
    float4 a = *(const float4*)(Op + p0 * HDIM + d4);
    float4 b = *(const float4*)(Op + p1 * HDIM + d4);
    float o[4] = { a.x * s0 + b.x * s1, a.y * s0 + b.y * s1,
                   a.z * s0 + b.z * s1, a.w * s0 + b.w * s1 };
    __nv_bfloat16 h4[4], l4[4];
    #pragma unroll
    for (int j = 0; j < 4; j++) {
        h4[j] = __float2bfloat16(o[j]);
        l4[j] = __float2bfloat16(o[j] - __bfloat162float(h4[j]));
    }
    size_t od = ((size_t)q * HID + h * HDIM + d4) >> 1;
    ((__nv_bfloat162*)aHi)[od]     = __nv_bfloat162(h4[0], h4[1]);
    ((__nv_bfloat162*)aHi)[od + 1] = __nv_bfloat162(h4[2], h4[3]);
    ((__nv_bfloat162*)aLo)[od]     = __nv_bfloat162(l4[0], l4[1]);
    ((__nv_bfloat162*)aLo)[od + 1] = __nv_bfloat162(l4[2], l4[3]);
}

// ---------------------------------------------------------------------------
// Launch (single stream, graph-safe)
// ---------------------------------------------------------------------------
extern "C" void kernel_launch(void* const* d_in, const int* in_sizes, int n_in,
                              void* d_out, int out_size)
{
    const float* hid = (const float*)d_in[0];
    const float* kc  = (const float*)d_in[1];
    const float* vc  = (const float*)d_in[2];
    const float* Wq  = (const float*)d_in[3];
    const float* bq  = (const float*)d_in[4];
    const float* Wk  = (const float*)d_in[5];
    const float* bk  = (const float*)d_in[6];
    const float* Wv  = (const float*)d_in[7];
    const float* bv  = (const float*)d_in[8];
    const float* Wo  = (const float*)d_in[9];
    const int*   pos = (const int*)d_in[10];
    float* out = (float*)d_out;

    float *gQ, *gK, *gV, *gOp, *gMl;
    cudaGetSymbolAddress((void**)&gQ, g_Q);
    cudaGetSymbolAddress((void**)&gK, g_K);
    cudaGetSymbolAddress((void**)&gV, g_V);
    cudaGetSymbolAddress((void**)&gOp, g_Op);
    cudaGetSymbolAddress((void**)&gMl, g_Ml);
    __nv_bfloat16 *hHi, *hLo, *aHi, *aLo;
    __nv_bfloat16 *qHi, *qLo, *kHi, *kLo, *vHi, *vLo, *oHi, *oLo;
    __nv_bfloat16 *QbH, *QbL, *KbH, *KbL, *VbH, *VbL;
    cudaGetSymbolAddress((void**)&hHi, g_hid_hi);
    cudaGetSymbolAddress((void**)&hLo, g_hid_lo);
    cudaGetSymbolAddress((void**)&aHi, g_att_hi);
    cudaGetSymbolAddress((void**)&aLo, g_att_lo);
    cudaGetSymbolAddress((void**)&qHi, g_WqT_hi);
    cudaGetSymbolAddress((void**)&qLo, g_WqT_lo);
    cudaGetSymbolAddress((void**)&kHi, g_WkT_hi);
    cudaGetSymbolAddress((void**)&kLo, g_WkT_lo);
    cudaGetSymbolAddress((void**)&vHi, g_WvT_hi);
    cudaGetSymbolAddress((void**)&vLo, g_WvT_lo);
    cudaGetSymbolAddress((void**)&oHi, g_WoT_hi);
    cudaGetSymbolAddress((void**)&oLo, g_WoT_lo);
    cudaGetSymbolAddress((void**)&QbH, g_Qb_hi);
    cudaGetSymbolAddress((void**)&QbL, g_Qb_lo);
    cudaGetSymbolAddress((void**)&KbH, g_Kb_hi);
    cudaGetSymbolAddress((void**)&KbL, g_Kb_lo);
    cudaGetSymbolAddress((void**)&VbH, g_Vb_hi);
    cudaGetSymbolAddress((void**)&VbL, g_Vb_lo);

    cudaFuncSetAttribute(qkv_mm_kernel, cudaFuncAttributeMaxDynamicSharedMemorySize, MM_SMEM);
    cudaFuncSetAttribute(oproj_kernel, cudaFuncAttributeMaxDynamicSharedMemorySize, MM_SMEM);
    cudaFuncSetAttribute(flash_mma_kernel, cudaFuncAttributeMaxDynamicSharedMemorySize, FL_SMEM);

    const int n4 = QLEN * HID / 4;

    // 1. operand preparation (transposes + hid split in one launch, then pack)
    prep_kernel<<<dim3(112, 112, 5), dim3(32, 8)>>>(
        Wq, Wk, Wv, Wo, hid, qHi, qLo, kHi, kLo, vHi, vLo, oHi, oLo, hHi, hLo);
    pack_kv_kernel<<<dim3((NKV * PASTLEN * 32 + 255) / 256, 2), 256>>>(
        kc, vc, KbH, KbL, VbH, VbL);

    // 2. fused QKV projections (2 CTAs/SM, 2-phase GEMM)
    qkv_mm_kernel<<<dim3(36, 8), 128, MM_SMEM>>>(hHi, hLo, qHi, qLo, kHi, kLo, vHi, vLo,
                                                 bq, bk, bv, gQ, gK, gV);

    // 3. RoPE + split packing of Q, new-K, new-V
    rope_pack_kernel<<<dim3(QLEN, 3), 256>>>(gQ, gK, gV, pos, QbH, QbL, KbH, KbL, VbH, VbL);

    // 4. attention (tensorized, 2-way KV split) + combine-with-split
    flash_mma_kernel<<<dim3(8, 28, 2), 256, FL_SMEM>>>(QbH, QbL, KbH, KbL, VbH, VbL, gOp, gMl);
    const int cn = NHEADS * QLEN * (HDIM / 4);
    combine_split_kernel<<<(cn + 255) / 256, 256>>>(gOp, gMl, aHi, aLo);

    // 5. output projection (split-K x2 into partials, then add)
    oproj_kernel<<<dim3(28, 8, 2), 128, MM_SMEM>>>(aHi, aLo, oHi, oLo, gOp);
    addout_kernel<<<(n4 + 255) / 256, 256>>>(gOp, out);
}

// round 16
// speedup vs baseline: 1.1481x; 1.1481x over previous
#include <cuda_runtime.h>
#include <cuda_bf16.h>
#include <cuda_fp16.h>
#include <cstdint>
#include <math.h>

// ---------------------------------------------------------------------------
// Problem constants
// ---------------------------------------------------------------------------
#define QLEN     1024
#define HID      3584
#define NHEADS   28
#define NKV      4
#define HDIM     128
#define PASTLEN  3072
#define KVTOT    4096
#define NREP     7

// ---------------------------------------------------------------------------
// Scratch (device globals)
// ---------------------------------------------------------------------------
__device__ float g_Q[QLEN * HID];
__device__ float g_K[QLEN * (NKV*HDIM)];
__device__ float g_V[QLEN * (NKV*HDIM)];

__device__ __nv_bfloat16 g_hid_hi[QLEN * HID];
__device__ __nv_bfloat16 g_hid_lo[QLEN * HID];
__device__ __nv_bfloat16 g_att_hi[QLEN * HID];
__device__ __nv_bfloat16 g_att_lo[QLEN * HID];
__device__ __nv_bfloat16 g_WqT_hi[HID * HID];
__device__ __nv_bfloat16 g_WqT_lo[HID * HID];
__device__ __nv_bfloat16 g_WkT_hi[(NKV*HDIM) * HID];
__device__ __nv_bfloat16 g_WkT_lo[(NKV*HDIM) * HID];
__device__ __nv_bfloat16 g_WvT_hi[(NKV*HDIM) * HID];
__device__ __nv_bfloat16 g_WvT_lo[(NKV*HDIM) * HID];
__device__ __nv_bfloat16 g_WoT_hi[HID * HID];
__device__ __nv_bfloat16 g_WoT_lo[HID * HID];

// attention operands (fp16: Q hi/lo, K single, V hi/lo)
__device__ __half g_Qb_hi[QLEN * HID];
__device__ __half g_Qb_lo[QLEN * HID];
__device__ __half g_Kb_hi[NKV * KVTOT * HDIM];
__device__ __half g_Vb_hi[NKV * KVTOT * HDIM];
__device__ __half g_Vb_lo[NKV * KVTOT * HDIM];

__device__ float g_Op[2 * NHEADS * QLEN * HDIM];
__device__ float g_Ml[2 * NHEADS * QLEN * 2];

// ---------------------------------------------------------------------------
// Helpers (plain-sm_103-legal: cp.async + ldmatrix + mma.sync only)
// ---------------------------------------------------------------------------
__device__ __forceinline__ uint32_t smem_to_u32(const void* p) {
    uint32_t a;
    asm("{ .reg .u64 t; cvta.to.shared.u64 t, %1; cvt.u32.u64 %0, t; }" : "=r"(a) : "l"(p));
    return a;
}
#define SMEM_SWIZZLE_128B(b) ((b) ^ (((b) >> 3) & 0x70))

__device__ __forceinline__ void cp_async16(uint32_t dst, const void* src) {
    asm volatile("cp.async.cg.shared.global [%0], [%1], 16;" :: "r"(dst), "l"(src) : "memory");
}
__device__ __forceinline__ void cp_commit() {
    asm volatile("cp.async.commit_group;" ::: "memory");
}
template <int N> __device__ __forceinline__ void cp_wait() {
    asm volatile("cp.async.wait_group %0;" :: "n"(N) : "memory");
}

__device__ __forceinline__ void ldm_x4(uint32_t* r, uint32_t addr) {
    asm volatile("ldmatrix.sync.aligned.m8n8.x4.shared.b16 {%0,%1,%2,%3}, [%4];"
                 : "=r"(r[0]), "=r"(r[1]), "=r"(r[2]), "=r"(r[3]) : "r"(addr));
}
__device__ __forceinline__ void ldm_x4t(uint32_t* r, uint32_t addr) {
    asm volatile("ldmatrix.sync.aligned.m8n8.x4.trans.shared.b16 {%0,%1,%2,%3}, [%4];"
                 : "=r"(r[0]), "=r"(r[1]), "=r"(r[2]), "=r"(r[3]) : "r"(addr));
}
__device__ __forceinline__ void mma_bf16(float* c, const uint32_t* a, const uint32_t* b) {
    asm volatile("mma.sync.aligned.m16n8k16.row.col.f32.bf16.bf16.f32 "
                 "{%0,%1,%2,%3}, {%4,%5,%6,%7}, {%8,%9}, {%0,%1,%2,%3};"
                 : "+f"(c[0]), "+f"(c[1]), "+f"(c[2]), "+f"(c[3])
                 : "r"(a[0]), "r"(a[1]), "r"(a[2]), "r"(a[3]), "r"(b[0]), "r"(b[1]));
}
__device__ __forceinline__ void mma_f16(float* c, const uint32_t* a, const uint32_t* b) {
    asm volatile("mma.sync.aligned.m16n8k16.row.col.f32.f16.f16.f32 "
                 "{%0,%1,%2,%3}, {%4,%5,%6,%7}, {%8,%9}, {%0,%1,%2,%3};"
                 : "+f"(c[0]), "+f"(c[1]), "+f"(c[2]), "+f"(c[3])
                 : "r"(a[0]), "r"(a[1]), "r"(a[2]), "r"(a[3]), "r"(b[0]), "r"(b[1]));
}
__device__ __forceinline__ float fexp2(float x) {
    float y; asm("ex2.approx.ftz.f32 %0, %1;" : "=f"(y) : "f"(x)); return y;
}
__device__ __forceinline__ uint32_t packh(__half a, __half b) {
    __half2 t = __halves2half2(a, b);
    return *(uint32_t*)&t;
}

// ---------------------------------------------------------------------------
// Weight transposes + hidden-state split in one launch.
// z 0..3: W [K=3584][N] f32 -> T [N][K] bf16 hi/lo.  z == 4: split(hid).
// ---------------------------------------------------------------------------
__global__ void prep_kernel(const float* __restrict__ Wq,
                            const float* __restrict__ Wk,
                            const float* __restrict__ Wv,
                            const float* __restrict__ Wo,
                            const float* __restrict__ hid,
                            __nv_bfloat16* __restrict__ qhi, __nv_bfloat16* __restrict__ qlo,
                            __nv_bfloat16* __restrict__ khi, __nv_bfloat16* __restrict__ klo,
                            __nv_bfloat16* __restrict__ vhi, __nv_bfloat16* __restrict__ vlo,
                            __nv_bfloat16* __restrict__ ohi, __nv_bfloat16* __restrict__ olo,
                            __nv_bfloat16* __restrict__ hhi, __nv_bfloat16* __restrict__ hlo)
{
    const int z = blockIdx.z;
    if (z == 4) {
        int b = blockIdx.y * 112 + blockIdx.x;
        if (b >= 3584) return;
        int i = b * 256 + threadIdx.y * 32 + threadIdx.x;
        float4 x = ((const float4*)hid)[i];
        float v[4] = { x.x, x.y, x.z, x.w };
        __nv_bfloat16 h[4], l[4];
        #pragma unroll
        for (int j = 0; j < 4; j++) {
            h[j] = __float2bfloat16(v[j]);
            l[j] = __float2bfloat16(v[j] - __bfloat162float(h[j]));
        }
        __nv_bfloat162* H = (__nv_bfloat162*)hhi;
        __nv_bfloat162* L = (__nv_bfloat162*)hlo;
        H[2*i]   = __nv_bfloat162(h[0], h[1]);
        H[2*i+1] = __nv_bfloat162(h[2], h[3]);
        L[2*i]   = __nv_bfloat162(l[0], l[1]);
        L[2*i+1] = __nv_bfloat162(l[2], l[3]);
        return;
    }

    const float* W; __nv_bfloat16 *Thi, *Tlo; int N;
    if      (z == 0) { W = Wq; Thi = qhi; Tlo = qlo; N = HID; }
    else if (z == 1) { W = Wk; Thi = khi; Tlo = klo; N = NKV*HDIM; }
    else if (z == 2) { W = Wv; Thi = vhi; Tlo = vlo; N = NKV*HDIM; }
    else             { W = Wo; Thi = ohi; Tlo = olo; N = HID; }
    if (blockIdx.x * 32 >= N) return;

    __shared__ float t[32][33];
    int n0 = blockIdx.x * 32, k0 = blockIdx.y * 32;
    int tx = threadIdx.x, ty = threadIdx.y;
    #pragma unroll
    for (int r = 0; r < 4; r++)
        t[ty + r*8][tx] = W[(size_t)(k0 + ty + r*8) * N + n0 + tx];
    __syncthreads();
    #pragma unroll
    for (int r = 0; r < 4; r++) {
        int n = n0 + ty + r*8;
        float v = t[tx][ty + r*8];
        __nv_bfloat16 h = __float2bfloat16(v);
        __nv_bfloat16 l = __float2bfloat16(v - __bfloat162float(h));
        Thi[(size_t)n * HID + k0 + tx] = h;
        Tlo[(size_t)n * HID + k0 + tx] = l;
    }
}

// Pack KV cache rows (fp16): y=0 K-cache (single), y=1 V-cache (hi/lo)
__global__ void pack_kv_kernel(const float* __restrict__ kcache,
                               const float* __restrict__ vcache,
                               __half* __restrict__ khi,
                               __half* __restrict__ vhi,
                               __half* __restrict__ vlo)
{
    int i = blockIdx.x * blockDim.x + threadIdx.x;
    if (i >= NKV * PASTLEN * 32) return;
    int kvh = i / (PASTLEN * 32);
    int rem = i % (PASTLEN * 32);
    int pos = rem >> 5;
    int d4  = (rem & 31) * 4;
    const float* cache = blockIdx.y ? vcache : kcache;
    float4 v = *(const float4*)(cache + ((size_t)(kvh * PASTLEN + pos) * HDIM + d4));
    float a[4] = { v.x, v.y, v.z, v.w };
    size_t o = ((size_t)(kvh * KVTOT + pos) * HDIM + d4) >> 1;
    if (blockIdx.y == 0) {
        __half2* H = (__half2*)khi;
        H[o]     = __halves2half2(__float2half_rn(a[0]), __float2half_rn(a[1]));
        H[o + 1] = __halves2half2(__float2half_rn(a[2]), __float2half_rn(a[3]));
    } else {
        __half h[4], l[4];
        #pragma unroll
        for (int j = 0; j < 4; j++) {
            h[j] = __float2half_rn(a[j]);
            l[j] = __float2half_rn(a[j] - __half2float(h[j]));
        }
        __half2* H = (__half2*)vhi;
        __half2* L = (__half2*)vlo;
        H[o]     = __halves2half2(h[0], h[1]);
        H[o + 1] = __halves2half2(h[2], h[3]);
        L[o]     = __halves2half2(l[0], l[1]);
        L[o + 1] = __halves2half2(l[2], l[3]);
    }
}

// ---------------------------------------------------------------------------
// mma.sync split-precision GEMM core v5 (R12 WIN, unchanged).
// ---------------------------------------------------------------------------
#define MM_SMEM  99328

__device__ __forceinline__ void mm_tile(
    const __nv_bfloat16* __restrict__ Ahi, const __nv_bfloat16* __restrict__ Alo,
    const __nv_bfloat16* __restrict__ Bhi, const __nv_bfloat16* __restrict__ Blo,
    const float* __restrict__ bias, float* __restrict__ C, int ldc,
    int m0, int n0, int kbase, int segst, char* smem)
{
    const uint32_t sb   = smem_to_u32(smem);
    const uint32_t DATA = (sb + 1023u) & ~1023u;
    const int tid = threadIdx.x, wid = tid >> 5, lane = tid & 31;
    const int wm = (wid & 1) * 64;
    const int wn = (wid >> 1) * 64;

    uint32_t sw8[8]; int gr8[8], gc8[8];
    #pragma unroll
    for (int i = 0; i < 8; i++) {
        int c = tid + i * 128;
        gr8[i] = c >> 3;
        gc8[i] = (c & 7) * 8;
        sw8[i] = SMEM_SWIZZLE_128B((uint32_t)((c >> 3) * 128 + (c & 7) * 16));
    }

    auto load1 = [&](int g) {
        int kk = kbase + g * 64;
        uint32_t ab = DATA + (uint32_t)(g & 1) * 49152u;
        #pragma unroll
        for (int i = 0; i < 8; i++)
            cp_async16(ab + sw8[i], Ahi + (size_t)(m0 + gr8[i]) * HID + kk + gc8[i]);
        #pragma unroll
        for (int i = 0; i < 8; i++)
            cp_async16(ab + 16384u + sw8[i], Bhi + (size_t)(n0 + gr8[i]) * HID + kk + gc8[i]);
        #pragma unroll
        for (int i = 0; i < 8; i++)
            cp_async16(ab + 32768u + sw8[i], Blo + (size_t)(n0 + gr8[i]) * HID + kk + gc8[i]);
        cp_commit();
    };
    auto load2 = [&](int g) {
        int kk = kbase + g * 64;
        uint32_t ab = DATA + (uint32_t)(g % 3) * 32768u;
        #pragma unroll
        for (int i = 0; i < 8; i++)
            cp_async16(ab + sw8[i], Alo + (size_t)(m0 + gr8[i]) * HID + kk + gc8[i]);
        #pragma unroll
        for (int i = 0; i < 8; i++)
            cp_async16(ab + 16384u + sw8[i], Bhi + (size_t)(n0 + gr8[i]) * HID + kk + gc8[i]);
        cp_commit();
    };

    float acc[4][8][4];
    #pragma unroll
    for (int a = 0; a < 4; a++)
        #pragma unroll
        for (int b = 0; b < 8; b++)
            #pragma unroll
            for (int c = 0; c < 4; c++) acc[a][b][c] = 0.0f;

    const int a_row = wm + (lane & 15);
    const int a_kb  = (lane >> 4) * 16;
    const int b_row = wn + ((lane >> 4) & 1) * 8 + (lane & 7);
    const int b_kb  = ((lane >> 3) & 1) * 16;

    // ---------------- phase 1: AhiBhi + AhiBlo ----------------
    load1(0);
    for (int g = 0; g < segst; g++) {
        cp_wait<0>();
        __syncthreads();
        if (g + 1 < segst) load1(g + 1);

        uint32_t ab = DATA + (uint32_t)(g & 1) * 49152u;

        #pragma unroll
        for (int ks = 0; ks < 4; ks++) {
            int kin = ks * 32;
            uint32_t aF[4][4];
            #pragma unroll
            for (int mi = 0; mi < 4; mi++) {
                uint32_t byte = (uint32_t)((a_row + mi * 16) * 128 + kin + a_kb);
                ldm_x4(aF[mi], ab + SMEM_SWIZZLE_128B(byte));
            }
            #pragma unroll
            for (int comp = 0; comp < 2; comp++) {
                uint32_t bb = ab + 16384u + (uint32_t)comp * 16384u;
                uint32_t bF[8][2];
                #pragma unroll
                for (int nb = 0; nb < 4; nb++) {
                    uint32_t byte = (uint32_t)((b_row + nb * 16) * 128 + kin + b_kb);
                    uint32_t r[4];
                    ldm_x4(r, bb + SMEM_SWIZZLE_128B(byte));
                    bF[nb*2+0][0] = r[0]; bF[nb*2+0][1] = r[1];
                    bF[nb*2+1][0] = r[2]; bF[nb*2+1][1] = r[3];
                }
                #pragma unroll
                for (int mi = 0; mi < 4; mi++)
                    #pragma unroll
                    for (int ni = 0; ni < 8; ni++)
                        mma_bf16(acc[mi][ni], aF[mi], bF[ni]);
            }
        }
    }
    __syncthreads();

    // ---------------- phase 2: AloBhi ----------------
    load2(0); load2(1);
    for (int g = 0; g < segst; g++) {
        if (g < segst - 1) cp_wait<1>();
        else               cp_wait<0>();
        __syncthreads();
        if (g + 2 < segst) load2(g + 2);

        uint32_t ab = DATA + (uint32_t)(g % 3) * 32768u;
        uint32_t bb = ab + 16384u;

        #pragma unroll
        for (int ks = 0; ks < 4; ks++) {
            int kin = ks * 32;
            uint32_t aF[4][4];
            #pragma unroll
            for (int mi = 0; mi < 4; mi++) {
                uint32_t byte = (uint32_t)((a_row + mi * 16) * 128 + kin + a_kb);
                ldm_x4(aF[mi], ab + SMEM_SWIZZLE_128B(byte));
            }
            uint32_t bF[8][2];
            #pragma unroll
            for (int nb = 0; nb < 4; nb++) {
                uint32_t byte = (uint32_t)((b_row + nb * 16) * 128 + kin + b_kb);
                uint32_t r[4];
                ldm_x4(r, bb + SMEM_SWIZZLE_128B(byte));
                bF[nb*2+0][0] = r[0]; bF[nb*2+0][1] = r[1];
                bF[nb*2+1][0] = r[2]; bF[nb*2+1][1] = r[3];
            }
            #pragma unroll
            for (int mi = 0; mi < 4; mi++)
                #pragma unroll
                for (int ni = 0; ni < 8; ni++)
                    mma_bf16(acc[mi][ni], aF[mi], bF[ni]);
        }
    }

    const int group = lane >> 2, tig = lane & 3;
    #pragma unroll
    for (int mi = 0; mi < 4; mi++) {
        #pragma unroll
        for (int ni = 0; ni < 8; ni++) {
            int r0 = m0 + wm + mi * 16 + group;
            int c0 = n0 + wn + ni * 8 + tig * 2;
            float b0 = 0.f, b1 = 0.f;
            if (bias) { b0 = bias[c0]; b1 = bias[c0 + 1]; }
            float2 v0 = make_float2(acc[mi][ni][0] + b0, acc[mi][ni][1] + b1);
            float2 v1 = make_float2(acc[mi][ni][2] + b0, acc[mi][ni][3] + b1);
            *(float2*)(C + (size_t)r0 * ldc + c0)       = v0;
            *(float2*)(C + (size_t)(r0 + 8) * ldc + c0) = v1;
        }
    }
}

// Fused QKV projection: grid (36, 8), 128 threads, 2 CTAs/SM
__global__ __launch_bounds__(128)
void qkv_mm_kernel(const __nv_bfloat16* __restrict__ Ahi, const __nv_bfloat16* __restrict__ Alo,
                   const __nv_bfloat16* __restrict__ qHi, const __nv_bfloat16* __restrict__ qLo,
                   const __nv_bfloat16* __restrict__ kHi, const __nv_bfloat16* __restrict__ kLo,
                   const __nv_bfloat16* __restrict__ vHi, const __nv_bfloat16* __restrict__ vLo,
                   const float* __restrict__ bq, const float* __restrict__ bk,
                   const float* __restrict__ bv,
                   float* __restrict__ gQ, float* __restrict__ gK, float* __restrict__ gV)
{
    extern __shared__ char smem[];
    const int bx = blockIdx.x, m0 = blockIdx.y * 128;
    if (bx < 28)
        mm_tile(Ahi, Alo, qHi, qLo, bq, gQ, HID, m0, bx * 128, 0, 56, smem);
    else if (bx < 32)
        mm_tile(Ahi, Alo, kHi, kLo, bk, gK, NKV*HDIM, m0, (bx - 28) * 128, 0, 56, smem);
    else
        mm_tile(Ahi, Alo, vHi, vLo, bv, gV, NKV*HDIM, m0, (bx - 32) * 128, 0, 56, smem);
}

// Output projection, split-K x2: grid (28, 8, 2) -> partial buffers
__global__ __launch_bounds__(128)
void oproj_kernel(const __nv_bfloat16* __restrict__ Ahi, const __nv_bfloat16* __restrict__ Alo,
                  const __nv_bfloat16* __restrict__ Bhi, const __nv_bfloat16* __restrict__ Blo,
                  float* __restrict__ P)
{
    extern __shared__ char smem[];
    const int z = blockIdx.z;
    mm_tile(Ahi, Alo, Bhi, Blo, nullptr, P + (size_t)z * QLEN * HID, HID,
            blockIdx.y * 128, blockIdx.x * 128, z * 1792, 28, smem);
}

// Sum the two split-K partials -> final output
__global__ void addout_kernel(const float* __restrict__ P, float* __restrict__ out)
{
    int i = blockIdx.x * blockDim.x + threadIdx.x;
    if (i >= QLEN * HID / 4) return;
    float4 a = ((const float4*)P)[i];
    float4 b = ((const float4*)(P + (size_t)QLEN * HID))[i];
    ((float4*)out)[i] = make_float4(a.x + b.x, a.y + b.y, a.z + b.z, a.w + b.w);
}

// ---------------------------------------------------------------------------
// RoPE + fp16 packing. y=0: Q rows (hi/lo); y=1: K rows (single fp16);
// y=2: V new rows (hi/lo).
// ---------------------------------------------------------------------------
__global__ void rope_pack_kernel(const float* __restrict__ gQ, const float* __restrict__ gK,
                                 const float* __restrict__ gV, const int* __restrict__ pos,
                                 __half* __restrict__ QbH, __half* __restrict__ QbL,
                                 __half* __restrict__ KbH,
                                 __half* __restrict__ VbH, __half* __restrict__ VbL)
{
    const int q = blockIdx.x;
    const int mode = blockIdx.y;

    if (mode == 2) {
        for (int t = threadIdx.x; t < NKV * HDIM; t += blockDim.x) {
            int kvh = t >> 7, d = t & 127;
            float v = gV[(size_t)q * (NKV*HDIM) + t];
            __half h = __float2half_rn(v);
            __half l = __float2half_rn(v - __half2float(h));
            size_t dd = ((size_t)kvh * KVTOT + PASTLEN + q) * HDIM + d;
            VbH[dd] = h; VbL[dd] = l;
        }
        return;
    }

    __shared__ float cs[64], sn[64];
    const float p = (float)pos[q];
    if (threadIdx.x < 64) {
        float e = (float)threadIdx.x * (1.0f / 64.0f);
        float invf = 1.0f / powf(1000000.0f, e);
        sincosf(p * invf, &sn[threadIdx.x], &cs[threadIdx.x]);
    }
    __syncthreads();

    const int isK = mode;
    const int nh = isK ? NKV : NHEADS;
    const float* src = isK ? (gK + (size_t)q * (NKV*HDIM)) : (gQ + (size_t)q * HID);

    for (int t = threadIdx.x; t < nh * 64; t += blockDim.x) {
        int hh = t >> 6, i = t & 63;
        float s = sn[i], c = cs[i];
        const float* base = src + hh * HDIM;
        float x1 = base[i];
        float x2 = base[i + 64];
        float o1 = x1 * c - x2 * s;
        float o2 = x2 * c + x1 * s;
        if (isK) {
            size_t row = (size_t)hh * KVTOT + PASTLEN + q;
            size_t d1 = row * HDIM + i, d2 = d1 + 64;
            KbH[d1] = __float2half_rn(o1);
            KbH[d2] = __float2half_rn(o2);
        } else {
            __half h1 = __float2half_rn(o1);
            __half l1 = __float2half_rn(o1 - __half2float(h1));
            __half h2 = __float2half_rn(o2);
            __half l2 = __float2half_rn(o2 - __half2float(h2));
            size_t d1 = (size_t)q * HID + hh * HDIM + i, d2 = d1 + 64;
            QbH[d1] = h1; QbL[d1] = l1;
            QbH[d2] = h2; QbL[d2] = l2;
        }
    }
}

// ---------------------------------------------------------------------------
// Tensorized flash attention v3 (fp16, 4 passes): 128 q x 64 kv, 256 threads.
// QK = (Qhi + Qlo) * K_f16  (2 mma passes);  PV = P_f16 * (Vhi + Vlo) (2 passes).
// smem: Q 64KB [Qhi 32K | Qlo 32K], 2-stage KV ring at 64K,
// stage 48KB = {Khi 16K | Vhi 16K | Vlo 16K}, panels of 8KB. Total 160KB.
// 2-way KV split; grid (8, 28, 2).
// ---------------------------------------------------------------------------
#define FL_SMEM 163840

__global__ __launch_bounds__(256, 1)
void flash_mma_kernel(const __half* __restrict__ Qhi,
                      const __half* __restrict__ Qlo,
                      const __half* __restrict__ Kbh,
                      const __half* __restrict__ Vbh,
                      const __half* __restrict__ Vbl,
                      float* __restrict__ Op, float* __restrict__ Ml)
{
    extern __shared__ char smraw[];
    const uint32_t sb = smem_to_u32(smraw);
    const int tid = threadIdx.x, wid = tid >> 5, lane = tid & 31;
    const int qt = blockIdx.x, h = blockIdx.y, z = blockIdx.z;
    const int kvh = h / NREP;
    const int q0 = qt * 128;
    const int w16 = wid * 16;
    const int nt = 50 + 2 * qt;
    const int t0 = z ? (nt >> 1) : 0;
    const int t1 = z ? nt : (nt >> 1);

    // ---- Q tile load (once): 2 comps x 2048 chunks ----
    #pragma unroll
    for (int i = 0; i < 16; i++) {
        int cg = tid + i * 256;
        int comp = i >> 3;
        int c = cg & 2047;
        int row = c >> 4, d8 = (c & 15) * 8;
        uint32_t dst = sb + (uint32_t)comp * 32768 + (uint32_t)((c >> 3) & 1) * 16384
                     + SMEM_SWIZZLE_128B((uint32_t)(row * 128 + (c & 7) * 16));
        const __half* src = (comp ? Qlo : Qhi);
        cp_async16(dst, src + (size_t)(q0 + row) * HID + h * HDIM + d8);
    }
    cp_commit();

    auto load_stage = [&](int t) {
        uint32_t base = sb + 65536u + (uint32_t)(t & 1) * 49152u;
        int kvbase = t * 64;
        #pragma unroll
        for (int i = 0; i < 12; i++) {       // 3 comps x 1024 chunks
            int comp = i >> 2;               // 0 Khi, 1 Vhi, 2 Vlo
            int c = (tid + i * 256) & 1023;
            int kv = c >> 4, d8 = (c & 15) * 8;
            uint32_t dst = base + (uint32_t)comp * 16384 + (uint32_t)((c >> 3) & 1) * 8192
                         + SMEM_SWIZZLE_128B((uint32_t)(kv * 128 + (c & 7) * 16));
            const __half* src = (comp == 0) ? Kbh : (comp == 1) ? Vbh : Vbl;
            cp_async16(dst, src + ((size_t)(kvh * KVTOT + kvbase + kv) * HDIM + d8));
        }
        cp_commit();
    };

    load_stage(t0);

    // ---- prologue: wait for Q (older group), register-cache Q frags ----
    cp_wait<1>();
    __syncthreads();
    uint32_t qFh[8][4], qFl[8][4];
    #pragma unroll
    for (int kc = 0; kc < 8; kc++) {
        uint32_t qoff = (uint32_t)((w16 + (lane & 15)) * 128 + (kc & 3) * 32 + (lane >> 4) * 16);
        uint32_t qa = sb + (uint32_t)(kc >> 2) * 16384 + SMEM_SWIZZLE_128B(qoff);
        ldm_x4(qFh[kc], qa);
        ldm_x4(qFl[kc], qa + 32768);
    }

    float Oacc[16][4];
    #pragma unroll
    for (int i = 0; i < 16; i++)
        #pragma unroll
        for (int j = 0; j < 4; j++) Oacc[i][j] = 0.0f;
    float m0 = -INFINITY, m1 = -INFINITY, l0 = 0.0f, l1 = 0.0f;

    const float SL = 0.08838834764831845f * 1.4426950408889634f;
    const int r0 = lane >> 2;

    for (int t = t0; t < t1; t++) {
        cp_wait<0>();
        __syncthreads();
        if (t + 1 < t1) load_stage(t + 1);

        const uint32_t stage = sb + 65536u + (uint32_t)(t & 1) * 49152u;
        const int kvbase = t * 64;

        // ---- S = (Qhi + Qlo) K  (2-pass fp16) ----
        float S[8][4];
        #pragma unroll
        for (int i = 0; i < 8; i++)
            #pragma unroll
            for (int j = 0; j < 4; j++) S[i][j] = 0.0f;

        #pragma unroll
        for (int kc = 0; kc < 8; kc++) {
            uint32_t kcol = (uint32_t)((kc & 3) * 32 + ((lane >> 3) & 1) * 16);
            #pragma unroll
            for (int np = 0; np < 4; np++) {
                uint32_t koff = (uint32_t)((np * 16 + ((lane >> 4) & 1) * 8 + (lane & 7)) * 128) + kcol;
                uint32_t ka = stage + (uint32_t)(kc >> 2) * 8192 + SMEM_SWIZZLE_128B(koff);
                uint32_t kh[4];
                ldm_x4(kh, ka);
                mma_f16(S[2*np],   qFh[kc], kh);     mma_f16(S[2*np],   qFl[kc], kh);
                mma_f16(S[2*np+1], qFh[kc], kh + 2); mma_f16(S[2*np+1], qFl[kc], kh + 2);
            }
        }

        // ---- causal mask (last two global tiles; z=1 only) ----
        if (t >= nt - 2) {
            const int lim0 = PASTLEN + q0 + w16 + r0;
            const int lim1 = lim0 + 8;
            #pragma unroll
            for (int nc = 0; nc < 8; nc++) {
                int col = kvbase + nc * 8 + (lane & 3) * 2;
                if (col     > lim0) S[nc][0] = -1e30f;
                if (col + 1 > lim0) S[nc][1] = -1e30f;
                if (col     > lim1) S[nc][2] = -1e30f;
                if (col + 1 > lim1) S[nc][3] = -1e30f;
            }
        }

        // ---- online softmax ----
        float mx0 = -INFINITY, mx1 = -INFINITY;
        #pragma unroll
        for (int nc = 0; nc < 8; nc++) {
            mx0 = fmaxf(mx0, fmaxf(S[nc][0], S[nc][1]));
            mx1 = fmaxf(mx1, fmaxf(S[nc][2], S[nc][3]));
        }
        mx0 = fmaxf(mx0, __shfl_xor_sync(0xffffffffu, mx0, 1));
        mx0 = fmaxf(mx0, __shfl_xor_sync(0xffffffffu, mx0, 2));
        mx1 = fmaxf(mx1, __shfl_xor_sync(0xffffffffu, mx1, 1));
        mx1 = fmaxf(mx1, __shfl_xor_sync(0xffffffffu, mx1, 2));
        float mn0 = fmaxf(m0, mx0 * SL);
        float mn1 = fmaxf(m1, mx1 * SL);
        float cor0 = fexp2(m0 - mn0);
        float cor1 = fexp2(m1 - mn1);
        m0 = mn0; m1 = mn1;

        uint32_t pF[8][2];
        float rs0 = 0.0f, rs1 = 0.0f;
        #pragma unroll
        for (int nc = 0; nc < 8; nc++) {
            float p0 = fexp2(S[nc][0] * SL - mn0);
            float p1 = fexp2(S[nc][1] * SL - mn0);
            float p2 = fexp2(S[nc][2] * SL - mn1);
            float p3 = fexp2(S[nc][3] * SL - mn1);
            rs0 += p0 + p1;  rs1 += p2 + p3;
            pF[nc][0] = packh(__float2half_rn(p0), __float2half_rn(p1));
            pF[nc][1] = packh(__float2half_rn(p2), __float2half_rn(p3));
        }
        rs0 += __shfl_xor_sync(0xffffffffu, rs0, 1);
        rs0 += __shfl_xor_sync(0xffffffffu, rs0, 2);
        rs1 += __shfl_xor_sync(0xffffffffu, rs1, 1);
        rs1 += __shfl_xor_sync(0xffffffffu, rs1, 2);
        l0 = l0 * cor0 + rs0;
        l1 = l1 * cor1 + rs1;

        #pragma unroll
        for (int nc = 0; nc < 16; nc++) {
            Oacc[nc][0] *= cor0; Oacc[nc][1] *= cor0;
            Oacc[nc][2] *= cor1; Oacc[nc][3] *= cor1;
        }

        // ---- O += P (Vhi + Vlo)  (2-pass fp16) ----
        #pragma unroll
        for (int kc = 0; kc < 4; kc++) {
            uint32_t aF[4] = { pF[2*kc][0], pF[2*kc][1], pF[2*kc+1][0], pF[2*kc+1][1] };
            uint32_t vrow = (uint32_t)(kc * 16 + ((lane >> 3) & 1) * 8 + (lane & 7));
            #pragma unroll
            for (int dp = 0; dp < 8; dp++) {
                uint32_t voff = vrow * 128 + (uint32_t)((dp & 3) * 32 + ((lane >> 4) & 1) * 16);
                uint32_t va = stage + 16384u + (uint32_t)(dp >> 2) * 8192 + SMEM_SWIZZLE_128B(voff);
                uint32_t vh[4], vl[4];
                ldm_x4t(vh, va);
                ldm_x4t(vl, va + 16384u);
                mma_f16(Oacc[2*dp],   aF, vh);     mma_f16(Oacc[2*dp],   aF, vl);
                mma_f16(Oacc[2*dp+1], aF, vh + 2); mma_f16(Oacc[2*dp+1], aF, vl + 2);
            }
        }
    }

    // ---- epilogue: write raw partials ----
    const int rowa = q0 + w16 + r0;
    const size_t pb = ((size_t)(z * NHEADS + h) * QLEN);
    #pragma unroll
    for (int nc = 0; nc < 16; nc++) {
        int col = nc * 8 + (lane & 3) * 2;
        *(float2*)(Op + (pb + rowa) * HDIM + col) =
            make_float2(Oacc[nc][0], Oacc[nc][1]);
        *(float2*)(Op + (pb + rowa + 8) * HDIM + col) =
            make_float2(Oacc[nc][2], Oacc[nc][3]);
    }
    if ((lane & 3) == 0) {
        Ml[(pb + rowa) * 2]     = m0;
        Ml[(pb + rowa) * 2 + 1] = l0;
        Ml[(pb + rowa + 8) * 2]     = m1;
        Ml[(pb + rowa + 8) * 2 + 1] = l1;
    }
}

// Merge the two KV-split partials -> split-bf16 attention output
__global__ void combine_split_kernel(const float* __restrict__ Op,
                                     const float* __restrict__ Ml,
                                     __nv_bfloat16* __restrict__ aHi,
                                     __nv_bfloat16* __restrict__ aLo)
{
    int i = blockIdx.x * blockDim.x + threadIdx.x;
    if (i >= NHEADS * QLEN * (HDIM / 4)) return;
    int hq = i >> 5;
    int d4 = (i & 31) * 4;
    int h = hq >> 10, q = hq & 1023;
    size_t p0 = (size_t)h * QLEN + q;
    size_t p1 = (size_t)(NHEADS + h) * QLEN + q;
    float m0 = Ml[p0 * 2], l0 = Ml[p0 * 2 + 1];
    float m1 = Ml[p1 * 2], l1 = Ml[p1 * 2 + 1];
    float m = fmaxf(m0, m1);
    float s0 = fexp2(m0 - m), s1 = fexp2(m1 - m);
    float inv = 1.0f / (l0 * s0 + l1 * s1);
    s0 *= inv; s1 *= inv;
    float4 a = *(const float4*)(Op + p0 * HDIM + d4);
    float4 b = *(const float4*)(Op + p1 * HDIM + d4);
    float o[4] = { a.x * s0 + b.x * s1, a.y * s0 + b.y * s1,
                   a.z * s0 + b.z * s1, a.w * s0 + b.w * s1 };
    __nv_bfloat16 h4[4], l4[4];
    #pragma unroll
    for (int j = 0; j < 4; j++) {
        h4[j] = __float2bfloat16(o[j]);
        l4[j] = __float2bfloat16(o[j] - __bfloat162float(h4[j]));
    }
    size_t od = ((size_t)q * HID + h * HDIM + d4) >> 1;
    ((__nv_bfloat162*)aHi)[od]     = __nv_bfloat162(h4[0], h4[1]);
    ((__nv_bfloat162*)aHi)[od + 1] = __nv_bfloat162(h4[2], h4[3]);
    ((__nv_bfloat162*)aLo)[od]     = __nv_bfloat162(l4[0], l4[1]);
    ((__nv_bfloat162*)aLo)[od + 1] = __nv_bfloat162(l4[2], l4[3]);
}

// ---------------------------------------------------------------------------
// Launch (single stream, graph-safe)
// ---------------------------------------------------------------------------
extern "C" void kernel_launch(void* const* d_in, const int* in_sizes, int n_in,
                              void* d_out, int out_size)
{
    const float* hid = (const float*)d_in[0];
    const float* kc  = (const float*)d_in[1];
    const float* vc  = (const float*)d_in[2];
    const float* Wq  = (const float*)d_in[3];
    const float* bq  = (const float*)d_in[4];
    const float* Wk  = (const float*)d_in[5];
    const float* bk  = (const float*)d_in[6];
    const float* Wv  = (const float*)d_in[7];
    const float* bv  = (const float*)d_in[8];
    const float* Wo  = (const float*)d_in[9];
    const int*   pos = (const int*)d_in[10];
    float* out = (float*)d_out;

    float *gQ, *gK, *gV, *gOp, *gMl;
    cudaGetSymbolAddress((void**)&gQ, g_Q);
    cudaGetSymbolAddress((void**)&gK, g_K);
    cudaGetSymbolAddress((void**)&gV, g_V);
    cudaGetSymbolAddress((void**)&gOp, g_Op);
    cudaGetSymbolAddress((void**)&gMl, g_Ml);
    __nv_bfloat16 *hHi, *hLo, *aHi, *aLo;
    __nv_bfloat16 *qHi, *qLo, *kHi, *kLo, *vHi, *vLo, *oHi, *oLo;
    __half *QbH, *QbL, *KbH, *VbH, *VbL;
    cudaGetSymbolAddress((void**)&hHi, g_hid_hi);
    cudaGetSymbolAddress((void**)&hLo, g_hid_lo);
    cudaGetSymbolAddress((void**)&aHi, g_att_hi);
    cudaGetSymbolAddress((void**)&aLo, g_att_lo);
    cudaGetSymbolAddress((void**)&qHi, g_WqT_hi);
    cudaGetSymbolAddress((void**)&qLo, g_WqT_lo);
    cudaGetSymbolAddress((void**)&kHi, g_WkT_hi);
    cudaGetSymbolAddress((void**)&kLo, g_WkT_lo);
    cudaGetSymbolAddress((void**)&vHi, g_WvT_hi);
    cudaGetSymbolAddress((void**)&vLo, g_WvT_lo);
    cudaGetSymbolAddress((void**)&oHi, g_WoT_hi);
    cudaGetSymbolAddress((void**)&oLo, g_WoT_lo);
    cudaGetSymbolAddress((void**)&QbH, g_Qb_hi);
    cudaGetSymbolAddress((void**)&QbL, g_Qb_lo);
    cudaGetSymbolAddress((void**)&KbH, g_Kb_hi);
    cudaGetSymbolAddress((void**)&VbH, g_Vb_hi);
    cudaGetSymbolAddress((void**)&VbL, g_Vb_lo);

    cudaFuncSetAttribute(qkv_mm_kernel, cudaFuncAttributeMaxDynamicSharedMemorySize, MM_SMEM);
    cudaFuncSetAttribute(oproj_kernel, cudaFuncAttributeMaxDynamicSharedMemorySize, MM_SMEM);
    cudaFuncSetAttribute(flash_mma_kernel, cudaFuncAttributeMaxDynamicSharedMemorySize, FL_SMEM);

    const int n4 = QLEN * HID / 4;

    // 1. operand preparation
    prep_kernel<<<dim3(112, 112, 5), dim3(32, 8)>>>(
        Wq, Wk, Wv, Wo, hid, qHi, qLo, kHi, kLo, vHi, vLo, oHi, oLo, hHi, hLo);
    pack_kv_kernel<<<dim3((NKV * PASTLEN * 32 + 255) / 256, 2), 256>>>(
        kc, vc, KbH, VbH, VbL);

    // 2. fused QKV projections (2 CTAs/SM, 2-phase GEMM)
    qkv_mm_kernel<<<dim3(36, 8), 128, MM_SMEM>>>(hHi, hLo, qHi, qLo, kHi, kLo, vHi, vLo,
                                                 bq, bk, bv, gQ, gK, gV);

    // 3. RoPE + fp16 packing of Q, new-K, new-V
    rope_pack_kernel<<<dim3(QLEN, 3), 256>>>(gQ, gK, gV, pos, QbH, QbL, KbH, VbH, VbL);

    // 4. attention (fp16 4-pass, 2-way KV split) + combine-with-split
    flash_mma_kernel<<<dim3(8, 28, 2), 256, FL_SMEM>>>(QbH, QbL, KbH, VbH, VbL, gOp, gMl);
    const int cn = NHEADS * QLEN * (HDIM / 4);
    combine_split_kernel<<<(cn + 255) / 256, 256>>>(gOp, gMl, aHi, aLo);

    // 5. output projection (split-K x2 into partials, then add)
    oproj_kernel<<<dim3(28, 8, 2), 128, MM_SMEM>>>(aHi, aLo, oHi, oLo, gOp);
    addout_kernel<<<(n4 + 255) / 256, 256>>>(gOp, out);
}

// round 17
// speedup vs baseline: 1.3687x; 1.1921x over previous
#include <cuda_runtime.h>
#include <cuda_bf16.h>
#include <cuda_fp16.h>
#include <cstdint>
#include <math.h>

// ---------------------------------------------------------------------------
// Problem constants
// ---------------------------------------------------------------------------
#define QLEN     1024
#define HID      3584
#define NHEADS   28
#define NKV      4
#define HDIM     128
#define PASTLEN  3072
#define KVTOT    4096
#define NREP     7

// ---------------------------------------------------------------------------
// Scratch (device globals)
// ---------------------------------------------------------------------------
__device__ float g_Q[QLEN * HID];
__device__ float g_K[QLEN * (NKV*HDIM)];
__device__ float g_V[QLEN * (NKV*HDIM)];

__device__ __nv_bfloat16 g_hid_hi[QLEN * HID];
__device__ __nv_bfloat16 g_hid_lo[QLEN * HID];
__device__ __nv_bfloat16 g_WqT_hi[HID * HID];
__device__ __nv_bfloat16 g_WqT_lo[HID * HID];
__device__ __nv_bfloat16 g_WkT_hi[(NKV*HDIM) * HID];
__device__ __nv_bfloat16 g_WkT_lo[(NKV*HDIM) * HID];
__device__ __nv_bfloat16 g_WvT_hi[(NKV*HDIM) * HID];
__device__ __nv_bfloat16 g_WvT_lo[(NKV*HDIM) * HID];

// O-projection operands (fp16 2-pass: A hi/lo, W single)
__device__ __half g_att_hi[QLEN * HID];
__device__ __half g_att_lo[QLEN * HID];
__device__ __half g_WoT[HID * HID];

// attention operands (fp16: Q hi/lo, K single, V single)
__device__ __half g_Qb_hi[QLEN * HID];
__device__ __half g_Qb_lo[QLEN * HID];
__device__ __half g_Kb_hi[NKV * KVTOT * HDIM];
__device__ __half g_Vb_hi[NKV * KVTOT * HDIM];

__device__ float g_Op[2 * NHEADS * QLEN * HDIM];
__device__ float g_Ml[2 * NHEADS * QLEN * 2];

// ---------------------------------------------------------------------------
// Helpers (plain-sm_103-legal: cp.async + ldmatrix + mma.sync only)
// ---------------------------------------------------------------------------
__device__ __forceinline__ uint32_t smem_to_u32(const void* p) {
    uint32_t a;
    asm("{ .reg .u64 t; cvta.to.shared.u64 t, %1; cvt.u32.u64 %0, t; }" : "=r"(a) : "l"(p));
    return a;
}
#define SMEM_SWIZZLE_128B(b) ((b) ^ (((b) >> 3) & 0x70))

__device__ __forceinline__ void cp_async16(uint32_t dst, const void* src) {
    asm volatile("cp.async.cg.shared.global [%0], [%1], 16;" :: "r"(dst), "l"(src) : "memory");
}
__device__ __forceinline__ void cp_commit() {
    asm volatile("cp.async.commit_group;" ::: "memory");
}
template <int N> __device__ __forceinline__ void cp_wait() {
    asm volatile("cp.async.wait_group %0;" :: "n"(N) : "memory");
}

__device__ __forceinline__ void ldm_x4(uint32_t* r, uint32_t addr) {
    asm volatile("ldmatrix.sync.aligned.m8n8.x4.shared.b16 {%0,%1,%2,%3}, [%4];"
                 : "=r"(r[0]), "=r"(r[1]), "=r"(r[2]), "=r"(r[3]) : "r"(addr));
}
__device__ __forceinline__ void ldm_x4t(uint32_t* r, uint32_t addr) {
    asm volatile("ldmatrix.sync.aligned.m8n8.x4.trans.shared.b16 {%0,%1,%2,%3}, [%4];"
                 : "=r"(r[0]), "=r"(r[1]), "=r"(r[2]), "=r"(r[3]) : "r"(addr));
}
__device__ __forceinline__ void mma_bf16(float* c, const uint32_t* a, const uint32_t* b) {
    asm volatile("mma.sync.aligned.m16n8k16.row.col.f32.bf16.bf16.f32 "
                 "{%0,%1,%2,%3}, {%4,%5,%6,%7}, {%8,%9}, {%0,%1,%2,%3};"
                 : "+f"(c[0]), "+f"(c[1]), "+f"(c[2]), "+f"(c[3])
                 : "r"(a[0]), "r"(a[1]), "r"(a[2]), "r"(a[3]), "r"(b[0]), "r"(b[1]));
}
__device__ __forceinline__ void mma_f16(float* c, const uint32_t* a, const uint32_t* b) {
    asm volatile("mma.sync.aligned.m16n8k16.row.col.f32.f16.f16.f32 "
                 "{%0,%1,%2,%3}, {%4,%5,%6,%7}, {%8,%9}, {%0,%1,%2,%3};"
                 : "+f"(c[0]), "+f"(c[1]), "+f"(c[2]), "+f"(c[3])
                 : "r"(a[0]), "r"(a[1]), "r"(a[2]), "r"(a[3]), "r"(b[0]), "r"(b[1]));
}
__device__ __forceinline__ float fexp2(float x) {
    float y; asm("ex2.approx.ftz.f32 %0, %1;" : "=f"(y) : "f"(x)); return y;
}
__device__ __forceinline__ uint32_t packh(__half a, __half b) {
    __half2 t = __halves2half2(a, b);
    return *(uint32_t*)&t;
}

// ---------------------------------------------------------------------------
// Weight transposes + hidden-state split in one launch.
// z 0..2: Wq/Wk/Wv f32 -> bf16 hi/lo [N][K].  z == 3: Wo -> single fp16.
// z == 4: split(hid) bf16 hi/lo.
// ---------------------------------------------------------------------------
__global__ void prep_kernel(const float* __restrict__ Wq,
                            const float* __restrict__ Wk,
                            const float* __restrict__ Wv,
                            const float* __restrict__ Wo,
                            const float* __restrict__ hid,
                            __nv_bfloat16* __restrict__ qhi, __nv_bfloat16* __restrict__ qlo,
                            __nv_bfloat16* __restrict__ khi, __nv_bfloat16* __restrict__ klo,
                            __nv_bfloat16* __restrict__ vhi, __nv_bfloat16* __restrict__ vlo,
                            __half* __restrict__ oT,
                            __nv_bfloat16* __restrict__ hhi, __nv_bfloat16* __restrict__ hlo)
{
    const int z = blockIdx.z;
    if (z == 4) {
        int b = blockIdx.y * 112 + blockIdx.x;
        if (b >= 3584) return;
        int i = b * 256 + threadIdx.y * 32 + threadIdx.x;
        float4 x = ((const float4*)hid)[i];
        float v[4] = { x.x, x.y, x.z, x.w };
        __nv_bfloat16 h[4], l[4];
        #pragma unroll
        for (int j = 0; j < 4; j++) {
            h[j] = __float2bfloat16(v[j]);
            l[j] = __float2bfloat16(v[j] - __bfloat162float(h[j]));
        }
        __nv_bfloat162* H = (__nv_bfloat162*)hhi;
        __nv_bfloat162* L = (__nv_bfloat162*)hlo;
        H[2*i]   = __nv_bfloat162(h[0], h[1]);
        H[2*i+1] = __nv_bfloat162(h[2], h[3]);
        L[2*i]   = __nv_bfloat162(l[0], l[1]);
        L[2*i+1] = __nv_bfloat162(l[2], l[3]);
        return;
    }

    __shared__ float t[32][33];
    int n0 = blockIdx.x * 32, k0 = blockIdx.y * 32;
    int tx = threadIdx.x, ty = threadIdx.y;

    if (z == 3) {                 // Wo -> single fp16 transpose
        #pragma unroll
        for (int r = 0; r < 4; r++)
            t[ty + r*8][tx] = Wo[(size_t)(k0 + ty + r*8) * HID + n0 + tx];
        __syncthreads();
        #pragma unroll
        for (int r = 0; r < 4; r++) {
            int n = n0 + ty + r*8;
            oT[(size_t)n * HID + k0 + tx] = __float2half_rn(t[tx][ty + r*8]);
        }
        return;
    }

    const float* W; __nv_bfloat16 *Thi, *Tlo; int N;
    if      (z == 0) { W = Wq; Thi = qhi; Tlo = qlo; N = HID; }
    else if (z == 1) { W = Wk; Thi = khi; Tlo = klo; N = NKV*HDIM; }
    else             { W = Wv; Thi = vhi; Tlo = vlo; N = NKV*HDIM; }
    if (blockIdx.x * 32 >= N) return;

    #pragma unroll
    for (int r = 0; r < 4; r++)
        t[ty + r*8][tx] = W[(size_t)(k0 + ty + r*8) * N + n0 + tx];
    __syncthreads();
    #pragma unroll
    for (int r = 0; r < 4; r++) {
        int n = n0 + ty + r*8;
        float v = t[tx][ty + r*8];
        __nv_bfloat16 h = __float2bfloat16(v);
        __nv_bfloat16 l = __float2bfloat16(v - __bfloat162float(h));
        Thi[(size_t)n * HID + k0 + tx] = h;
        Tlo[(size_t)n * HID + k0 + tx] = l;
    }
}

// Pack KV cache rows (single fp16): y=0 K-cache, y=1 V-cache
__global__ void pack_kv_kernel(const float* __restrict__ kcache,
                               const float* __restrict__ vcache,
                               __half* __restrict__ khi,
                               __half* __restrict__ vhi)
{
    int i = blockIdx.x * blockDim.x + threadIdx.x;
    if (i >= NKV * PASTLEN * 32) return;
    int kvh = i / (PASTLEN * 32);
    int rem = i % (PASTLEN * 32);
    int pos = rem >> 5;
    int d4  = (rem & 31) * 4;
    const float* cache = blockIdx.y ? vcache : kcache;
    __half* dst = blockIdx.y ? vhi : khi;
    float4 v = *(const float4*)(cache + ((size_t)(kvh * PASTLEN + pos) * HDIM + d4));
    size_t o = ((size_t)(kvh * KVTOT + pos) * HDIM + d4) >> 1;
    __half2* H = (__half2*)dst;
    H[o]     = __halves2half2(__float2half_rn(v.x), __float2half_rn(v.y));
    H[o + 1] = __halves2half2(__float2half_rn(v.z), __float2half_rn(v.w));
}

// ---------------------------------------------------------------------------
// mma.sync split-precision bf16 GEMM core v5 (R12 WIN, unchanged) — QKV only.
// ---------------------------------------------------------------------------
#define MM_SMEM  99328

__device__ __forceinline__ void mm_tile(
    const __nv_bfloat16* __restrict__ Ahi, const __nv_bfloat16* __restrict__ Alo,
    const __nv_bfloat16* __restrict__ Bhi, const __nv_bfloat16* __restrict__ Blo,
    const float* __restrict__ bias, float* __restrict__ C, int ldc,
    int m0, int n0, int kbase, int segst, char* smem)
{
    const uint32_t sb   = smem_to_u32(smem);
    const uint32_t DATA = (sb + 1023u) & ~1023u;
    const int tid = threadIdx.x, wid = tid >> 5, lane = tid & 31;
    const int wm = (wid & 1) * 64;
    const int wn = (wid >> 1) * 64;

    uint32_t sw8[8]; int gr8[8], gc8[8];
    #pragma unroll
    for (int i = 0; i < 8; i++) {
        int c = tid + i * 128;
        gr8[i] = c >> 3;
        gc8[i] = (c & 7) * 8;
        sw8[i] = SMEM_SWIZZLE_128B((uint32_t)((c >> 3) * 128 + (c & 7) * 16));
    }

    auto load1 = [&](int g) {
        int kk = kbase + g * 64;
        uint32_t ab = DATA + (uint32_t)(g & 1) * 49152u;
        #pragma unroll
        for (int i = 0; i < 8; i++)
            cp_async16(ab + sw8[i], Ahi + (size_t)(m0 + gr8[i]) * HID + kk + gc8[i]);
        #pragma unroll
        for (int i = 0; i < 8; i++)
            cp_async16(ab + 16384u + sw8[i], Bhi + (size_t)(n0 + gr8[i]) * HID + kk + gc8[i]);
        #pragma unroll
        for (int i = 0; i < 8; i++)
            cp_async16(ab + 32768u + sw8[i], Blo + (size_t)(n0 + gr8[i]) * HID + kk + gc8[i]);
        cp_commit();
    };
    auto load2 = [&](int g) {
        int kk = kbase + g * 64;
        uint32_t ab = DATA + (uint32_t)(g % 3) * 32768u;
        #pragma unroll
        for (int i = 0; i < 8; i++)
            cp_async16(ab + sw8[i], Alo + (size_t)(m0 + gr8[i]) * HID + kk + gc8[i]);
        #pragma unroll
        for (int i = 0; i < 8; i++)
            cp_async16(ab + 16384u + sw8[i], Bhi + (size_t)(n0 + gr8[i]) * HID + kk + gc8[i]);
        cp_commit();
    };

    float acc[4][8][4];
    #pragma unroll
    for (int a = 0; a < 4; a++)
        #pragma unroll
        for (int b = 0; b < 8; b++)
            #pragma unroll
            for (int c = 0; c < 4; c++) acc[a][b][c] = 0.0f;

    const int a_row = wm + (lane & 15);
    const int a_kb  = (lane >> 4) * 16;
    const int b_row = wn + ((lane >> 4) & 1) * 8 + (lane & 7);
    const int b_kb  = ((lane >> 3) & 1) * 16;

    // ---------------- phase 1: AhiBhi + AhiBlo ----------------
    load1(0);
    for (int g = 0; g < segst; g++) {
        cp_wait<0>();
        __syncthreads();
        if (g + 1 < segst) load1(g + 1);

        uint32_t ab = DATA + (uint32_t)(g & 1) * 49152u;

        #pragma unroll
        for (int ks = 0; ks < 4; ks++) {
            int kin = ks * 32;
            uint32_t aF[4][4];
            #pragma unroll
            for (int mi = 0; mi < 4; mi++) {
                uint32_t byte = (uint32_t)((a_row + mi * 16) * 128 + kin + a_kb);
                ldm_x4(aF[mi], ab + SMEM_SWIZZLE_128B(byte));
            }
            #pragma unroll
            for (int comp = 0; comp < 2; comp++) {
                uint32_t bb = ab + 16384u + (uint32_t)comp * 16384u;
                uint32_t bF[8][2];
                #pragma unroll
                for (int nb = 0; nb < 4; nb++) {
                    uint32_t byte = (uint32_t)((b_row + nb * 16) * 128 + kin + b_kb);
                    uint32_t r[4];
                    ldm_x4(r, bb + SMEM_SWIZZLE_128B(byte));
                    bF[nb*2+0][0] = r[0]; bF[nb*2+0][1] = r[1];
                    bF[nb*2+1][0] = r[2]; bF[nb*2+1][1] = r[3];
                }
                #pragma unroll
                for (int mi = 0; mi < 4; mi++)
                    #pragma unroll
                    for (int ni = 0; ni < 8; ni++)
                        mma_bf16(acc[mi][ni], aF[mi], bF[ni]);
            }
        }
    }
    __syncthreads();

    // ---------------- phase 2: AloBhi ----------------
    load2(0); load2(1);
    for (int g = 0; g < segst; g++) {
        if (g < segst - 1) cp_wait<1>();
        else               cp_wait<0>();
        __syncthreads();
        if (g + 2 < segst) load2(g + 2);

        uint32_t ab = DATA + (uint32_t)(g % 3) * 32768u;
        uint32_t bb = ab + 16384u;

        #pragma unroll
        for (int ks = 0; ks < 4; ks++) {
            int kin = ks * 32;
            uint32_t aF[4][4];
            #pragma unroll
            for (int mi = 0; mi < 4; mi++) {
                uint32_t byte = (uint32_t)((a_row + mi * 16) * 128 + kin + a_kb);
                ldm_x4(aF[mi], ab + SMEM_SWIZZLE_128B(byte));
            }
            uint32_t bF[8][2];
            #pragma unroll
            for (int nb = 0; nb < 4; nb++) {
                uint32_t byte = (uint32_t)((b_row + nb * 16) * 128 + kin + b_kb);
                uint32_t r[4];
                ldm_x4(r, bb + SMEM_SWIZZLE_128B(byte));
                bF[nb*2+0][0] = r[0]; bF[nb*2+0][1] = r[1];
                bF[nb*2+1][0] = r[2]; bF[nb*2+1][1] = r[3];
            }
            #pragma unroll
            for (int mi = 0; mi < 4; mi++)
                #pragma unroll
                for (int ni = 0; ni < 8; ni++)
                    mma_bf16(acc[mi][ni], aF[mi], bF[ni]);
        }
    }

    const int group = lane >> 2, tig = lane & 3;
    #pragma unroll
    for (int mi = 0; mi < 4; mi++) {
        #pragma unroll
        for (int ni = 0; ni < 8; ni++) {
            int r0 = m0 + wm + mi * 16 + group;
            int c0 = n0 + wn + ni * 8 + tig * 2;
            float b0 = 0.f, b1 = 0.f;
            if (bias) { b0 = bias[c0]; b1 = bias[c0 + 1]; }
            float2 v0 = make_float2(acc[mi][ni][0] + b0, acc[mi][ni][1] + b1);
            float2 v1 = make_float2(acc[mi][ni][2] + b0, acc[mi][ni][3] + b1);
            *(float2*)(C + (size_t)r0 * ldc + c0)       = v0;
            *(float2*)(C + (size_t)(r0 + 8) * ldc + c0) = v1;
        }
    }
}

// Fused QKV projection: grid (36, 8), 128 threads, 2 CTAs/SM
__global__ __launch_bounds__(128)
void qkv_mm_kernel(const __nv_bfloat16* __restrict__ Ahi, const __nv_bfloat16* __restrict__ Alo,
                   const __nv_bfloat16* __restrict__ qHi, const __nv_bfloat16* __restrict__ qLo,
                   const __nv_bfloat16* __restrict__ kHi, const __nv_bfloat16* __restrict__ kLo,
                   const __nv_bfloat16* __restrict__ vHi, const __nv_bfloat16* __restrict__ vLo,
                   const float* __restrict__ bq, const float* __restrict__ bk,
                   const float* __restrict__ bv,
                   float* __restrict__ gQ, float* __restrict__ gK, float* __restrict__ gV)
{
    extern __shared__ char smem[];
    const int bx = blockIdx.x, m0 = blockIdx.y * 128;
    if (bx < 28)
        mm_tile(Ahi, Alo, qHi, qLo, bq, gQ, HID, m0, bx * 128, 0, 56, smem);
    else if (bx < 32)
        mm_tile(Ahi, Alo, kHi, kLo, bk, gK, NKV*HDIM, m0, (bx - 28) * 128, 0, 56, smem);
    else
        mm_tile(Ahi, Alo, vHi, vLo, bv, gV, NKV*HDIM, m0, (bx - 32) * 128, 0, 56, smem);
}

// ---------------------------------------------------------------------------
// fp16 2-pass O-projection: C = (Ahi + Alo) @ W^T. Split-K x2.
// Stage {Ahi 16K | Alo 16K | W 16K} = 48KB, 2-ring, 2 mma passes/stage.
// grid (28, 8, 2), 128 threads, 2 CTAs/SM.
// ---------------------------------------------------------------------------
__global__ __launch_bounds__(128)
void oproj_kernel(const __half* __restrict__ Ahi, const __half* __restrict__ Alo,
                  const __half* __restrict__ B, float* __restrict__ P)
{
    extern __shared__ char smem[];
    const uint32_t sb   = smem_to_u32(smem);
    const uint32_t DATA = (sb + 1023u) & ~1023u;
    const int tid = threadIdx.x, wid = tid >> 5, lane = tid & 31;
    const int wm = (wid & 1) * 64;
    const int wn = (wid >> 1) * 64;
    const int m0 = blockIdx.y * 128, n0 = blockIdx.x * 128;
    const int z = blockIdx.z;
    const int kbase = z * 1792;
    const int NST = 28;

    uint32_t sw8[8]; int gr8[8], gc8[8];
    #pragma unroll
    for (int i = 0; i < 8; i++) {
        int c = tid + i * 128;
        gr8[i] = c >> 3;
        gc8[i] = (c & 7) * 8;
        sw8[i] = SMEM_SWIZZLE_128B((uint32_t)((c >> 3) * 128 + (c & 7) * 16));
    }

    auto load_stage = [&](int g) {
        int kk = kbase + g * 64;
        uint32_t ab = DATA + (uint32_t)(g & 1) * 49152u;
        #pragma unroll
        for (int i = 0; i < 8; i++)
            cp_async16(ab + sw8[i], Ahi + (size_t)(m0 + gr8[i]) * HID + kk + gc8[i]);
        #pragma unroll
        for (int i = 0; i < 8; i++)
            cp_async16(ab + 16384u + sw8[i], Alo + (size_t)(m0 + gr8[i]) * HID + kk + gc8[i]);
        #pragma unroll
        for (int i = 0; i < 8; i++)
            cp_async16(ab + 32768u + sw8[i], B + (size_t)(n0 + gr8[i]) * HID + kk + gc8[i]);
        cp_commit();
    };

    float acc[4][8][4];
    #pragma unroll
    for (int a = 0; a < 4; a++)
        #pragma unroll
        for (int b = 0; b < 8; b++)
            #pragma unroll
            for (int c = 0; c < 4; c++) acc[a][b][c] = 0.0f;

    const int a_row = wm + (lane & 15);
    const int a_kb  = (lane >> 4) * 16;
    const int b_row = wn + ((lane >> 4) & 1) * 8 + (lane & 7);
    const int b_kb  = ((lane >> 3) & 1) * 16;

    load_stage(0);
    for (int g = 0; g < NST; g++) {
        cp_wait<0>();
        __syncthreads();
        if (g + 1 < NST) load_stage(g + 1);

        uint32_t ab = DATA + (uint32_t)(g & 1) * 49152u;
        uint32_t bb = ab + 32768u;

        #pragma unroll
        for (int ks = 0; ks < 4; ks++) {
            int kin = ks * 32;
            uint32_t aFh[4][4], aFl[4][4];
            #pragma unroll
            for (int mi = 0; mi < 4; mi++) {
                uint32_t byte = (uint32_t)((a_row + mi * 16) * 128 + kin + a_kb);
                uint32_t sw = SMEM_SWIZZLE_128B(byte);
                ldm_x4(aFh[mi], ab + sw);
                ldm_x4(aFl[mi], ab + 16384u + sw);
            }
            uint32_t bF[8][2];
            #pragma unroll
            for (int nb = 0; nb < 4; nb++) {
                uint32_t byte = (uint32_t)((b_row + nb * 16) * 128 + kin + b_kb);
                uint32_t r[4];
                ldm_x4(r, bb + SMEM_SWIZZLE_128B(byte));
                bF[nb*2+0][0] = r[0]; bF[nb*2+0][1] = r[1];
                bF[nb*2+1][0] = r[2]; bF[nb*2+1][1] = r[3];
            }
            #pragma unroll
            for (int mi = 0; mi < 4; mi++)
                #pragma unroll
                for (int ni = 0; ni < 8; ni++) {
                    mma_f16(acc[mi][ni], aFh[mi], bF[ni]);
                    mma_f16(acc[mi][ni], aFl[mi], bF[ni]);
                }
        }
    }

    float* C = P + (size_t)z * QLEN * HID;
    const int group = lane >> 2, tig = lane & 3;
    #pragma unroll
    for (int mi = 0; mi < 4; mi++) {
        #pragma unroll
        for (int ni = 0; ni < 8; ni++) {
            int r0 = m0 + wm + mi * 16 + group;
            int c0 = n0 + wn + ni * 8 + tig * 2;
            *(float2*)(C + (size_t)r0 * HID + c0) =
                make_float2(acc[mi][ni][0], acc[mi][ni][1]);
            *(float2*)(C + (size_t)(r0 + 8) * HID + c0) =
                make_float2(acc[mi][ni][2], acc[mi][ni][3]);
        }
    }
}

// Sum the two split-K partials -> final output
__global__ void addout_kernel(const float* __restrict__ P, float* __restrict__ out)
{
    int i = blockIdx.x * blockDim.x + threadIdx.x;
    if (i >= QLEN * HID / 4) return;
    float4 a = ((const float4*)P)[i];
    float4 b = ((const float4*)(P + (size_t)QLEN * HID))[i];
    ((float4*)out)[i] = make_float4(a.x + b.x, a.y + b.y, a.z + b.z, a.w + b.w);
}

// ---------------------------------------------------------------------------
// RoPE + fp16 packing. y=0: Q rows (hi/lo); y=1: K rows (single);
// y=2: V new rows (single).
// ---------------------------------------------------------------------------
__global__ void rope_pack_kernel(const float* __restrict__ gQ, const float* __restrict__ gK,
                                 const float* __restrict__ gV, const int* __restrict__ pos,
                                 __half* __restrict__ QbH, __half* __restrict__ QbL,
                                 __half* __restrict__ KbH, __half* __restrict__ VbH)
{
    const int q = blockIdx.x;
    const int mode = blockIdx.y;

    if (mode == 2) {
        for (int t = threadIdx.x; t < NKV * HDIM; t += blockDim.x) {
            int kvh = t >> 7, d = t & 127;
            float v = gV[(size_t)q * (NKV*HDIM) + t];
            size_t dd = ((size_t)kvh * KVTOT + PASTLEN + q) * HDIM + d;
            VbH[dd] = __float2half_rn(v);
        }
        return;
    }

    __shared__ float cs[64], sn[64];
    const float p = (float)pos[q];
    if (threadIdx.x < 64) {
        float e = (float)threadIdx.x * (1.0f / 64.0f);
        float invf = 1.0f / powf(1000000.0f, e);
        sincosf(p * invf, &sn[threadIdx.x], &cs[threadIdx.x]);
    }
    __syncthreads();

    const int isK = mode;
    const int nh = isK ? NKV : NHEADS;
    const float* src = isK ? (gK + (size_t)q * (NKV*HDIM)) : (gQ + (size_t)q * HID);

    for (int t = threadIdx.x; t < nh * 64; t += blockDim.x) {
        int hh = t >> 6, i = t & 63;
        float s = sn[i], c = cs[i];
        const float* base = src + hh * HDIM;
        float x1 = base[i];
        float x2 = base[i + 64];
        float o1 = x1 * c - x2 * s;
        float o2 = x2 * c + x1 * s;
        if (isK) {
            size_t row = (size_t)hh * KVTOT + PASTLEN + q;
            size_t d1 = row * HDIM + i, d2 = d1 + 64;
            KbH[d1] = __float2half_rn(o1);
            KbH[d2] = __float2half_rn(o2);
        } else {
            __half h1 = __float2half_rn(o1);
            __half l1 = __float2half_rn(o1 - __half2float(h1));
            __half h2 = __float2half_rn(o2);
            __half l2 = __float2half_rn(o2 - __half2float(h2));
            size_t d1 = (size_t)q * HID + hh * HDIM + i, d2 = d1 + 64;
            QbH[d1] = h1; QbL[d1] = l1;
            QbH[d2] = h2; QbL[d2] = l2;
        }
    }
}

// ---------------------------------------------------------------------------
// Tensorized flash attention v4 (fp16, 3 passes): 128 q x 64 kv, 256 threads.
// QK = (Qhi + Qlo) * K (2 passes);  PV = P * V (1 pass).
// smem: Q 64KB [Qhi 32K | Qlo 32K], 2-stage KV ring at 64K,
// stage 32KB = {Khi 16K | Vhi 16K}. Total 128KB. grid (8, 28, 2).
// ---------------------------------------------------------------------------
#define FL_SMEM 131072

__global__ __launch_bounds__(256, 1)
void flash_mma_kernel(const __half* __restrict__ Qhi,
                      const __half* __restrict__ Qlo,
                      const __half* __restrict__ Kbh,
                      const __half* __restrict__ Vbh,
                      float* __restrict__ Op, float* __restrict__ Ml)
{
    extern __shared__ char smraw[];
    const uint32_t sb = smem_to_u32(smraw);
    const int tid = threadIdx.x, wid = tid >> 5, lane = tid & 31;
    const int qt = blockIdx.x, h = blockIdx.y, z = blockIdx.z;
    const int kvh = h / NREP;
    const int q0 = qt * 128;
    const int w16 = wid * 16;
    const int nt = 50 + 2 * qt;
    const int t0 = z ? (nt >> 1) : 0;
    const int t1 = z ? nt : (nt >> 1);

    // ---- Q tile load (once): 2 comps x 2048 chunks ----
    #pragma unroll
    for (int i = 0; i < 16; i++) {
        int cg = tid + i * 256;
        int comp = i >> 3;
        int c = cg & 2047;
        int row = c >> 4, d8 = (c & 15) * 8;
        uint32_t dst = sb + (uint32_t)comp * 32768 + (uint32_t)((c >> 3) & 1) * 16384
                     + SMEM_SWIZZLE_128B((uint32_t)(row * 128 + (c & 7) * 16));
        const __half* src = (comp ? Qlo : Qhi);
        cp_async16(dst, src + (size_t)(q0 + row) * HID + h * HDIM + d8);
    }
    cp_commit();

    auto load_stage = [&](int t) {
        uint32_t base = sb + 65536u + (uint32_t)(t & 1) * 32768u;
        int kvbase = t * 64;
        #pragma unroll
        for (int i = 0; i < 8; i++) {        // 2 comps x 1024 chunks
            int comp = i >> 2;               // 0 Khi, 1 Vhi
            int c = (tid + i * 256) & 1023;
            int kv = c >> 4, d8 = (c & 15) * 8;
            uint32_t dst = base + (uint32_t)comp * 16384 + (uint32_t)((c >> 3) & 1) * 8192
                         + SMEM_SWIZZLE_128B((uint32_t)(kv * 128 + (c & 7) * 16));
            const __half* src = (comp == 0) ? Kbh : Vbh;
            cp_async16(dst, src + ((size_t)(kvh * KVTOT + kvbase + kv) * HDIM + d8));
        }
        cp_commit();
    };

    load_stage(t0);

    // ---- prologue: wait for Q (older group), register-cache Q frags ----
    cp_wait<1>();
    __syncthreads();
    uint32_t qFh[8][4], qFl[8][4];
    #pragma unroll
    for (int kc = 0; kc < 8; kc++) {
        uint32_t qoff = (uint32_t)((w16 + (lane & 15)) * 128 + (kc & 3) * 32 + (lane >> 4) * 16);
        uint32_t qa = sb + (uint32_t)(kc >> 2) * 16384 + SMEM_SWIZZLE_128B(qoff);
        ldm_x4(qFh[kc], qa);
        ldm_x4(qFl[kc], qa + 32768);
    }

    float Oacc[16][4];
    #pragma unroll
    for (int i = 0; i < 16; i++)
        #pragma unroll
        for (int j = 0; j < 4; j++) Oacc[i][j] = 0.0f;
    float m0 = -INFINITY, m1 = -INFINITY, l0 = 0.0f, l1 = 0.0f;

    const float SL = 0.08838834764831845f * 1.4426950408889634f;
    const int r0 = lane >> 2;

    for (int t = t0; t < t1; t++) {
        cp_wait<0>();
        __syncthreads();
        if (t + 1 < t1) load_stage(t + 1);

        const uint32_t stage = sb + 65536u + (uint32_t)(t & 1) * 32768u;
        const int kvbase = t * 64;

        // ---- S = (Qhi + Qlo) K  (2-pass fp16) ----
        float S[8][4];
        #pragma unroll
        for (int i = 0; i < 8; i++)
            #pragma unroll
            for (int j = 0; j < 4; j++) S[i][j] = 0.0f;

        #pragma unroll
        for (int kc = 0; kc < 8; kc++) {
            uint32_t kcol = (uint32_t)((kc & 3) * 32 + ((lane >> 3) & 1) * 16);
            #pragma unroll
            for (int np = 0; np < 4; np++) {
                uint32_t koff = (uint32_t)((np * 16 + ((lane >> 4) & 1) * 8 + (lane & 7)) * 128) + kcol;
                uint32_t ka = stage + (uint32_t)(kc >> 2) * 8192 + SMEM_SWIZZLE_128B(koff);
                uint32_t kh[4];
                ldm_x4(kh, ka);
                mma_f16(S[2*np],   qFh[kc], kh);     mma_f16(S[2*np],   qFl[kc], kh);
                mma_f16(S[2*np+1], qFh[kc], kh + 2); mma_f16(S[2*np+1], qFl[kc], kh + 2);
            }
        }

        // ---- causal mask (last two global tiles; z=1 only) ----
        if (t >= nt - 2) {
            const int lim0 = PASTLEN + q0 + w16 + r0;
            const int lim1 = lim0 + 8;
            #pragma unroll
            for (int nc = 0; nc < 8; nc++) {
                int col = kvbase + nc * 8 + (lane & 3) * 2;
                if (col     > lim0) S[nc][0] = -1e30f;
                if (col + 1 > lim0) S[nc][1] = -1e30f;
                if (col     > lim1) S[nc][2] = -1e30f;
                if (col + 1 > lim1) S[nc][3] = -1e30f;
            }
        }

        // ---- online softmax ----
        float mx0 = -INFINITY, mx1 = -INFINITY;
        #pragma unroll
        for (int nc = 0; nc < 8; nc++) {
            mx0 = fmaxf(mx0, fmaxf(S[nc][0], S[nc][1]));
            mx1 = fmaxf(mx1, fmaxf(S[nc][2], S[nc][3]));
        }
        mx0 = fmaxf(mx0, __shfl_xor_sync(0xffffffffu, mx0, 1));
        mx0 = fmaxf(mx0, __shfl_xor_sync(0xffffffffu, mx0, 2));
        mx1 = fmaxf(mx1, __shfl_xor_sync(0xffffffffu, mx1, 1));
        mx1 = fmaxf(mx1, __shfl_xor_sync(0xffffffffu, mx1, 2));
        float mn0 = fmaxf(m0, mx0 * SL);
        float mn1 = fmaxf(m1, mx1 * SL);
        float cor0 = fexp2(m0 - mn0);
        float cor1 = fexp2(m1 - mn1);
        m0 = mn0; m1 = mn1;

        uint32_t pF[8][2];
        float rs0 = 0.0f, rs1 = 0.0f;
        #pragma unroll
        for (int nc = 0; nc < 8; nc++) {
            float p0 = fexp2(S[nc][0] * SL - mn0);
            float p1 = fexp2(S[nc][1] * SL - mn0);
            float p2 = fexp2(S[nc][2] * SL - mn1);
            float p3 = fexp2(S[nc][3] * SL - mn1);
            rs0 += p0 + p1;  rs1 += p2 + p3;
            pF[nc][0] = packh(__float2half_rn(p0), __float2half_rn(p1));
            pF[nc][1] = packh(__float2half_rn(p2), __float2half_rn(p3));
        }
        rs0 += __shfl_xor_sync(0xffffffffu, rs0, 1);
        rs0 += __shfl_xor_sync(0xffffffffu, rs0, 2);
        rs1 += __shfl_xor_sync(0xffffffffu, rs1, 1);
        rs1 += __shfl_xor_sync(0xffffffffu, rs1, 2);
        l0 = l0 * cor0 + rs0;
        l1 = l1 * cor1 + rs1;

        #pragma unroll
        for (int nc = 0; nc < 16; nc++) {
            Oacc[nc][0] *= cor0; Oacc[nc][1] *= cor0;
            Oacc[nc][2] *= cor1; Oacc[nc][3] *= cor1;
        }

        // ---- O += P V (1-pass fp16) ----
        #pragma unroll
        for (int kc = 0; kc < 4; kc++) {
            uint32_t aF[4] = { pF[2*kc][0], pF[2*kc][1], pF[2*kc+1][0], pF[2*kc+1][1] };
            uint32_t vrow = (uint32_t)(kc * 16 + ((lane >> 3) & 1) * 8 + (lane & 7));
            #pragma unroll
            for (int dp = 0; dp < 8; dp++) {
                uint32_t voff = vrow * 128 + (uint32_t)((dp & 3) * 32 + ((lane >> 4) & 1) * 16);
                uint32_t va = stage + 16384u + (uint32_t)(dp >> 2) * 8192 + SMEM_SWIZZLE_128B(voff);
                uint32_t vh[4];
                ldm_x4t(vh, va);
                mma_f16(Oacc[2*dp],   aF, vh);
                mma_f16(Oacc[2*dp+1], aF, vh + 2);
            }
        }
    }

    // ---- epilogue: write raw partials ----
    const int rowa = q0 + w16 + r0;
    const size_t pb = ((size_t)(z * NHEADS + h) * QLEN);
    #pragma unroll
    for (int nc = 0; nc < 16; nc++) {
        int col = nc * 8 + (lane & 3) * 2;
        *(float2*)(Op + (pb + rowa) * HDIM + col) =
            make_float2(Oacc[nc][0], Oacc[nc][1]);
        *(float2*)(Op + (pb + rowa + 8) * HDIM + col) =
            make_float2(Oacc[nc][2], Oacc[nc][3]);
    }
    if ((lane & 3) == 0) {
        Ml[(pb + rowa) * 2]     = m0;
        Ml[(pb + rowa) * 2 + 1] = l0;
        Ml[(pb + rowa + 8) * 2]     = m1;
        Ml[(pb + rowa + 8) * 2 + 1] = l1;
    }
}

// Merge the two KV-split partials -> fp16 hi/lo attention output (oproj A)
__global__ void combine_split_kernel(const float* __restrict__ Op,
                                     const float* __restrict__ Ml,
                                     __half* __restrict__ aHi,
                                     __half* __restrict__ aLo)
{
    int i = blockIdx.x * blockDim.x + threadIdx.x;
    if (i >= NHEADS * QLEN * (HDIM / 4)) return;
    int hq = i >> 5;
    int d4 = (i & 31) * 4;
    int h = hq >> 10, q = hq & 1023;
    size_t p0 = (size_t)h * QLEN + q;
    size_t p1 = (size_t)(NHEADS + h) * QLEN + q;
    float m0 = Ml[p0 * 2], l0 = Ml[p0 * 2 + 1];
    float m1 = Ml[p1 * 2], l1 = Ml[p1 * 2 + 1];
    float m = fmaxf(m0, m1);
    float s0 = fexp2(m0 - m), s1 = fexp2(m1 - m);
    float inv = 1.0f / (l0 * s0 + l1 * s1);
    s0 *= inv; s1 *= inv;
    float4 a = *(const float4*)(Op + p0 * HDIM + d4);
    float4 b = *(const float4*)(Op + p1 * HDIM + d4);
    float o[4] = { a.x * s0 + b.x * s1, a.y * s0 + b.y * s1,
                   a.z * s0 + b.z * s1, a.w * s0 + b.w * s1 };
    __half h4[4], l4[4];
    #pragma unroll
    for (int j = 0; j < 4; j++) {
        h4[j] = __float2half_rn(o[j]);
        l4[j] = __float2half_rn(o[j] - __half2float(h4[j]));
    }
    size_t od = ((size_t)q * HID + h * HDIM + d4) >> 1;
    ((__half2*)aHi)[od]     = __halves2half2(h4[0], h4[1]);
    ((__half2*)aHi)[od + 1] = __halves2half2(h4[2], h4[3]);
    ((__half2*)aLo)[od]     = __halves2half2(l4[0], l4[1]);
    ((__half2*)aLo)[od + 1] = __halves2half2(l4[2], l4[3]);
}

// ---------------------------------------------------------------------------
// Launch (single stream, graph-safe)
// ---------------------------------------------------------------------------
extern "C" void kernel_launch(void* const* d_in, const int* in_sizes, int n_in,
                              void* d_out, int out_size)
{
    const float* hid = (const float*)d_in[0];
    const float* kc  = (const float*)d_in[1];
    const float* vc  = (const float*)d_in[2];
    const float* Wq  = (const float*)d_in[3];
    const float* bq  = (const float*)d_in[4];
    const float* Wk  = (const float*)d_in[5];
    const float* bk  = (const float*)d_in[6];
    const float* Wv  = (const float*)d_in[7];
    const float* bv  = (const float*)d_in[8];
    const float* Wo  = (const float*)d_in[9];
    const int*   pos = (const int*)d_in[10];
    float* out = (float*)d_out;

    float *gQ, *gK, *gV, *gOp, *gMl;
    cudaGetSymbolAddress((void**)&gQ, g_Q);
    cudaGetSymbolAddress((void**)&gK, g_K);
    cudaGetSymbolAddress((void**)&gV, g_V);
    cudaGetSymbolAddress((void**)&gOp, g_Op);
    cudaGetSymbolAddress((void**)&gMl, g_Ml);
    __nv_bfloat16 *hHi, *hLo;
    __nv_bfloat16 *qHi, *qLo, *kHi, *kLo, *vHi, *vLo;
    __half *aHi, *aLo, *oT, *QbH, *QbL, *KbH, *VbH;
    cudaGetSymbolAddress((void**)&hHi, g_hid_hi);
    cudaGetSymbolAddress((void**)&hLo, g_hid_lo);
    cudaGetSymbolAddress((void**)&aHi, g_att_hi);
    cudaGetSymbolAddress((void**)&aLo, g_att_lo);
    cudaGetSymbolAddress((void**)&qHi, g_WqT_hi);
    cudaGetSymbolAddress((void**)&qLo, g_WqT_lo);
    cudaGetSymbolAddress((void**)&kHi, g_WkT_hi);
    cudaGetSymbolAddress((void**)&kLo, g_WkT_lo);
    cudaGetSymbolAddress((void**)&vHi, g_WvT_hi);
    cudaGetSymbolAddress((void**)&vLo, g_WvT_lo);
    cudaGetSymbolAddress((void**)&oT,  g_WoT);
    cudaGetSymbolAddress((void**)&QbH, g_Qb_hi);
    cudaGetSymbolAddress((void**)&QbL, g_Qb_lo);
    cudaGetSymbolAddress((void**)&KbH, g_Kb_hi);
    cudaGetSymbolAddress((void**)&VbH, g_Vb_hi);

    cudaFuncSetAttribute(qkv_mm_kernel, cudaFuncAttributeMaxDynamicSharedMemorySize, MM_SMEM);
    cudaFuncSetAttribute(oproj_kernel, cudaFuncAttributeMaxDynamicSharedMemorySize, MM_SMEM);
    cudaFuncSetAttribute(flash_mma_kernel, cudaFuncAttributeMaxDynamicSharedMemorySize, FL_SMEM);

    const int n4 = QLEN * HID / 4;

    // 1. operand preparation
    prep_kernel<<<dim3(112, 112, 5), dim3(32, 8)>>>(
        Wq, Wk, Wv, Wo, hid, qHi, qLo, kHi, kLo, vHi, vLo, oT, hHi, hLo);
    pack_kv_kernel<<<dim3((NKV * PASTLEN * 32 + 255) / 256, 2), 256>>>(
        kc, vc, KbH, VbH);

    // 2. fused QKV projections (bf16 3-pass, 2 CTAs/SM)
    qkv_mm_kernel<<<dim3(36, 8), 128, MM_SMEM>>>(hHi, hLo, qHi, qLo, kHi, kLo, vHi, vLo,
                                                 bq, bk, bv, gQ, gK, gV);

    // 3. RoPE + fp16 packing of Q, new-K, new-V
    rope_pack_kernel<<<dim3(QLEN, 3), 256>>>(gQ, gK, gV, pos, QbH, QbL, KbH, VbH);

    // 4. attention (fp16 3-pass, 2-way KV split) + combine-with-split
    flash_mma_kernel<<<dim3(8, 28, 2), 256, FL_SMEM>>>(QbH, QbL, KbH, VbH, gOp, gMl);
    const int cn = NHEADS * QLEN * (HDIM / 4);
    combine_split_kernel<<<(cn + 255) / 256, 256>>>(gOp, gMl, aHi, aLo);

    // 5. output projection (fp16 2-pass, split-K x2, then add)
    oproj_kernel<<<dim3(28, 8, 2), 128, MM_SMEM>>>(aHi, aLo, oT, gOp);
    addout_kernel<<<(n4 + 255) / 256, 256>>>(gOp, out);
}